// round 9
// baseline (speedup 1.0000x reference)
#include <cuda_runtime.h>
#include <cstdint>

#define THREADS 384
#define NW 12           // warps per block (3 per SMSP)
#define GRID 152

typedef unsigned long long ull;

__device__ __forceinline__ ull pk2(float lo, float hi) {
  ull r; asm("mov.b64 %0, {%1, %2};" : "=l"(r) : "f"(lo), "f"(hi)); return r;
}
__device__ __forceinline__ void unpk2(ull v, float& lo, float& hi) {
  asm("mov.b64 {%0, %1}, %2;" : "=f"(lo), "=f"(hi) : "l"(v));
}
__device__ __forceinline__ ull fma2(ull a, ull b, ull c) {
  ull d; asm("fma.rn.f32x2 %0, %1, %2, %3;" : "=l"(d) : "l"(a), "l"(b), "l"(c)); return d;
}

// ~222 KB dynamic shared memory, 1 block (12 warps) per SM.
// Head scratch (pooled/mps/c2s) aliases into H (dead ranges don't overlap in time).
struct Smem {
  alignas(16) float2 Wd[3][64][64];   // layers 1-3 DUPLICATED: Wd[l][k][f] = (W[f][k], W[f][k])
  alignas(16) float2 Wp4[64][20];     // layer 4 feature-pairs: 0..16 real (34 outs), 17..19 zero
  alignas(16) float2 Bd2[3][64];      // duplicated biases
  alignas(16) float2 Bp4[20];
  float  cw1t[5][16];     // [q][c]
  float  cb1[16];
  float  cw2t[16][5][32]; // [ci][q][c2]
  float  cb2[32];
  float  Wo[704];
  float  bo2[2];
  alignas(16) float  Hx[NW][2048];    // per-warp: H[64 feats][32 nodes], word-rotated; head aliased
};

// H addressing: row f = 128B = 8 x 16B words; logical word j (nodes 4j..4j+3)
// lives at physical word (j + (f>>3)) & 7. Float index of word start:
__device__ __forceinline__ int hword(int f, int j) {
  return f * 32 + (((j + (f >> 3)) & 7) << 2);
}

// Layers 1-3, node-packed: warp = 32 nodes x 64 feats; lane = 8 nodes x 8 feats.
// nl = lane&3 (nodes 8nl..8nl+7), ol = lane>>2 (feats 8ol..8ol+7).
// Per k: 2 act LDS.128 (pre-packed node pairs, zero movs) + 4 dup-weight LDS.128 + 32 FMA2.
__device__ __forceinline__ void mlp_np(const float2* __restrict__ Wd,   // [64][64] duplicated
                                       const float2* __restrict__ Bd,   // [64] duplicated
                                       float* __restrict__ Hw,          // [2048]
                                       int nl, int ol) {
  ull acc[4][8];
  {
    const ulonglong2* bb = reinterpret_cast<const ulonglong2*>(Bd + 8 * ol);
#pragma unroll
    for (int q = 0; q < 4; q++) {
      ulonglong2 b = bb[q];
#pragma unroll
      for (int n = 0; n < 4; n++) { acc[n][2 * q] = b.x; acc[n][2 * q + 1] = b.y; }
    }
  }
#pragma unroll 8
  for (int k = 0; k < 64; k++) {
    int kb = k >> 3;
    int w0 = (2 * nl + kb) & 7, w1 = (2 * nl + 1 + kb) & 7;
    const float* Hrow = Hw + k * 32;
    ulonglong2 av0 = *reinterpret_cast<const ulonglong2*>(Hrow + (w0 << 2)); // nodes 8nl..8nl+3
    ulonglong2 av1 = *reinterpret_cast<const ulonglong2*>(Hrow + (w1 << 2)); // nodes 8nl+4..8nl+7
    const ulonglong2* wr = reinterpret_cast<const ulonglong2*>(Wd + k * 64 + 8 * ol);
    ulonglong2 q0 = wr[0], q1 = wr[1], q2 = wr[2], q3 = wr[3];   // feats 8ol..8ol+7 duplicated
#pragma unroll
    for (int pp = 0; pp < 1; pp++) {  // (structured for clarity; fully unrolled below)
      acc[0][0] = fma2(av0.x, q0.x, acc[0][0]);
      acc[1][0] = fma2(av0.y, q0.x, acc[1][0]);
      acc[2][0] = fma2(av1.x, q0.x, acc[2][0]);
      acc[3][0] = fma2(av1.y, q0.x, acc[3][0]);
      acc[0][1] = fma2(av0.x, q0.y, acc[0][1]);
      acc[1][1] = fma2(av0.y, q0.y, acc[1][1]);
      acc[2][1] = fma2(av1.x, q0.y, acc[2][1]);
      acc[3][1] = fma2(av1.y, q0.y, acc[3][1]);
      acc[0][2] = fma2(av0.x, q1.x, acc[0][2]);
      acc[1][2] = fma2(av0.y, q1.x, acc[1][2]);
      acc[2][2] = fma2(av1.x, q1.x, acc[2][2]);
      acc[3][2] = fma2(av1.y, q1.x, acc[3][2]);
      acc[0][3] = fma2(av0.x, q1.y, acc[0][3]);
      acc[1][3] = fma2(av0.y, q1.y, acc[1][3]);
      acc[2][3] = fma2(av1.x, q1.y, acc[2][3]);
      acc[3][3] = fma2(av1.y, q1.y, acc[3][3]);
      acc[0][4] = fma2(av0.x, q2.x, acc[0][4]);
      acc[1][4] = fma2(av0.y, q2.x, acc[1][4]);
      acc[2][4] = fma2(av1.x, q2.x, acc[2][4]);
      acc[3][4] = fma2(av1.y, q2.x, acc[3][4]);
      acc[0][5] = fma2(av0.x, q2.y, acc[0][5]);
      acc[1][5] = fma2(av0.y, q2.y, acc[1][5]);
      acc[2][5] = fma2(av1.x, q2.y, acc[2][5]);
      acc[3][5] = fma2(av1.y, q2.y, acc[3][5]);
      acc[0][6] = fma2(av0.x, q3.x, acc[0][6]);
      acc[1][6] = fma2(av0.y, q3.x, acc[1][6]);
      acc[2][6] = fma2(av1.x, q3.x, acc[2][6]);
      acc[3][6] = fma2(av1.y, q3.x, acc[3][6]);
      acc[0][7] = fma2(av0.x, q3.y, acc[0][7]);
      acc[1][7] = fma2(av0.y, q3.y, acc[1][7]);
      acc[2][7] = fma2(av1.x, q3.y, acc[2][7]);
      acc[3][7] = fma2(av1.y, q3.y, acc[3][7]);
    }
  }
  // relu + writeback: feat f = 8ol+p; nodes 8nl..8nl+3 -> logical word 2nl, etc.
#pragma unroll
  for (int p = 0; p < 8; p++) {
    int f = 8 * ol + p;
    float a0, a1, b0, b1, c0, c1, d0, d1;
    unpk2(acc[0][p], a0, a1); unpk2(acc[1][p], b0, b1);
    unpk2(acc[2][p], c0, c1); unpk2(acc[3][p], d0, d1);
    float4 v0 = make_float4(fmaxf(a0, 0.f), fmaxf(a1, 0.f), fmaxf(b0, 0.f), fmaxf(b1, 0.f));
    float4 v1 = make_float4(fmaxf(c0, 0.f), fmaxf(c1, 0.f), fmaxf(d0, 0.f), fmaxf(d1, 0.f));
    *reinterpret_cast<float4*>(Hw + hword(f, 2 * nl))     = v0;
    *reinterpret_cast<float4*>(Hw + hword(f, 2 * nl + 1)) = v1;
  }
}

__global__ void __launch_bounds__(THREADS, 1) dgcnn_kernel(
    const float* __restrict__ x,
    const float* __restrict__ W1, const float* __restrict__ b1,
    const float* __restrict__ W2, const float* __restrict__ b2,
    const float* __restrict__ W3, const float* __restrict__ b3,
    const float* __restrict__ W4, const float* __restrict__ b4,
    const float* __restrict__ cw1, const float* __restrict__ cb1,
    const float* __restrict__ cw2, const float* __restrict__ cb2,
    const float* __restrict__ Wo, const float* __restrict__ bo,
    float* __restrict__ out, int G, int P)
{
  extern __shared__ __align__(16) char smem_raw[];
  Smem& s = *reinterpret_cast<Smem*>(smem_raw);
  const int tid  = threadIdx.x;
  const int w    = tid >> 5;
  const int lane = tid & 31;

  // ---- Stage weights once per block ----
  for (int idx = tid; idx < 3 * 64 * 64; idx += THREADS) {
    int l = idx >> 12, rem = idx & 4095, k = rem >> 6, f = rem & 63;
    const float* Wg = (l == 0) ? W1 : (l == 1) ? W2 : W3;
    float v = Wg[f * 64 + k];
    s.Wd[l][k][f] = make_float2(v, v);
  }
  for (int idx = tid; idx < 3 * 64; idx += THREADS) {
    int l = idx >> 6, f = idx & 63;
    const float* bg = (l == 0) ? b1 : (l == 1) ? b2 : b3;
    float v = bg[f];
    s.Bd2[l][f] = make_float2(v, v);
  }
  for (int idx = tid; idx < 64 * 20; idx += THREADS) {
    int k = idx / 20, p = idx % 20;
    s.Wp4[k][p] = (p < 17)
        ? make_float2(W4[(2 * p) * 64 + k], W4[(2 * p + 1) * 64 + k])
        : make_float2(0.f, 0.f);
  }
  if (tid < 20)
    s.Bp4[tid] = (tid < 17) ? make_float2(b4[2 * tid], b4[2 * tid + 1])
                            : make_float2(0.f, 0.f);
  for (int i = tid; i < 80; i += THREADS) { int q = i >> 4, c = i & 15; s.cw1t[q][c] = cw1[c * 5 + q]; }
  if (tid < 16)  s.cb1[tid] = cb1[tid];
  for (int i = tid; i < 2560; i += THREADS) {
    int ci = i / 160, r = i % 160, q = r >> 5, c2 = r & 31;
    s.cw2t[ci][q][c2] = cw2[(c2 * 16 + ci) * 5 + q];
  }
  if (tid < 32)  s.cb2[tid] = cb2[tid];
  for (int i = tid; i < 704; i += THREADS) s.Wo[i] = Wo[i];
  if (tid < 2)   s.bo2[tid] = bo[tid];
  __syncthreads();

  const int kc = (P < 30) ? P : 30;
  const float inv = 1.f / (float)kc;
  float* Hw = s.Hx[w];
  // head scratch aliased into Hw (H dead after layer-4 k-loop):
  float* pooled = Hw;          // 40 floats
  float* mpsb   = Hw + 64;     // [16][16]
  float* c2sb   = Hw + 320;    // 352 floats
  const int nl = lane & 3, ol = lane >> 2;      // layers 1-3 mapping
  const int nl4 = lane & 15, ol4 = lane >> 4;   // layer-4 mapping

  for (int g = blockIdx.x * NW + w; g < G; g += GRID * NW) {
    // ---- Load x rows into H (feature-major rows, word-rotated); pad nodes -> 0 ----
    {
      int src = (lane < kc) ? lane : 0;
      const float4* xr = reinterpret_cast<const float4*>(x + ((size_t)g * P + src) * 64);
      bool act = lane < kc;
      int jw = lane >> 2, off = lane & 3;
#pragma unroll
      for (int q = 0; q < 16; q++) {
        float4 v = act ? xr[q] : make_float4(0.f, 0.f, 0.f, 0.f);
        int f0 = 4 * q;
        Hw[(f0 + 0) * 32 + (((jw + ((f0 + 0) >> 3)) & 7) << 2) + off] = v.x;
        Hw[(f0 + 1) * 32 + (((jw + ((f0 + 1) >> 3)) & 7) << 2) + off] = v.y;
        Hw[(f0 + 2) * 32 + (((jw + ((f0 + 2) >> 3)) & 7) << 2) + off] = v.z;
        Hw[(f0 + 3) * 32 + (((jw + ((f0 + 3) >> 3)) & 7) << 2) + off] = v.w;
      }
    }
    __syncwarp();

    // ---- Layers 1-3 (node-packed, duplicated weights) ----
    mlp_np(&s.Wd[0][0][0], &s.Bd2[0][0], Hw, nl, ol);
    mlp_np(&s.Wd[1][0][0], &s.Bd2[1][0], Hw, nl, ol);
    mlp_np(&s.Wd[2][0][0], &s.Bd2[2][0], Hw, nl, ol);

    // ---- Layer 4 (feature-packed, 2 nodes x 10 pairs per lane) + pooling ----
    {
      ull acc[2][10];
#pragma unroll
      for (int p = 0; p < 10; p++) {
        float2 b = s.Bp4[10 * ol4 + p];
        ull bb = pk2(b.x, b.y);
        acc[0][p] = bb; acc[1][p] = bb;
      }
#pragma unroll 8
      for (int k = 0; k < 64; k++) {
        int kb = k >> 3;
        const float2 hv = *reinterpret_cast<const float2*>(
            Hw + k * 32 + ((((nl4 >> 1) + kb) & 7) << 2) + 2 * (nl4 & 1));
        ull h0 = pk2(hv.x, hv.x), h1 = pk2(hv.y, hv.y);
        const ulonglong2* wr = reinterpret_cast<const ulonglong2*>(&s.Wp4[k][10 * ol4]);
#pragma unroll
        for (int qq = 0; qq < 5; qq++) {
          ulonglong2 wp = wr[qq];
          acc[0][2*qq]   = fma2(h0, wp.x, acc[0][2*qq]);
          acc[1][2*qq]   = fma2(h1, wp.x, acc[1][2*qq]);
          acc[0][2*qq+1] = fma2(h0, wp.y, acc[0][2*qq+1]);
          acc[1][2*qq+1] = fma2(h1, wp.y, acc[1][2*qq+1]);
        }
      }
      // relu + node mask + mean-pool via butterfly
      float m0 = (2 * nl4     < kc) ? 1.f : 0.f;
      float m1 = (2 * nl4 + 1 < kc) ? 1.f : 0.f;
      float se[10], so[10];
#pragma unroll
      for (int p = 0; p < 10; p++) {
        float a0e, a0o, a1e, a1o;
        unpk2(acc[0][p], a0e, a0o);
        unpk2(acc[1][p], a1e, a1o);
        se[p] = m0 * fmaxf(a0e, 0.f) + m1 * fmaxf(a1e, 0.f);
        so[p] = m0 * fmaxf(a0o, 0.f) + m1 * fmaxf(a1o, 0.f);
      }
#pragma unroll
      for (int d = 1; d < 16; d <<= 1) {
#pragma unroll
        for (int p = 0; p < 10; p++) {
          se[p] += __shfl_xor_sync(0xffffffffu, se[p], d);
          so[p] += __shfl_xor_sync(0xffffffffu, so[p], d);
        }
      }
      __syncwarp();                 // all lanes done reading H before pooled overwrites it
      if (nl4 == 0) {
#pragma unroll
        for (int p = 0; p < 10; p++) {
          int f = 20 * ol4 + 2 * p;
          if (f < 34) {
            pooled[f]     = se[p] * inv;
            pooled[f + 1] = so[p] * inv;
          }
        }
      }
    }
    __syncwarp();

    // ---- conv1 (16ch,k=5 -> 30) + ReLU + maxpool2 -> mpsb[16][16] ----
    {
      int c = lane & 15, h = lane >> 4;
      float wq[5];
#pragma unroll
      for (int q = 0; q < 5; q++) wq[q] = s.cw1t[q][c];
      float bc = s.cb1[c];
#pragma unroll
      for (int sIdx = 0; sIdx < 15; sIdx++) {
        int t = 2 * sIdx + h;
        float a = bc;
#pragma unroll
        for (int q = 0; q < 5; q++) a = fmaf(wq[q], pooled[t + q], a);
        a = fmaxf(a, 0.f);
        float mv = fmaxf(a, __shfl_xor_sync(0xffffffffu, a, 16));
        if (h == 0) mpsb[c * 16 + sIdx] = mv;
      }
    }
    __syncwarp();

    // ---- conv2 (32ch,16in,k=5 -> 11) + ReLU ----
    {
      int c2 = lane;
      float a11[11];
#pragma unroll
      for (int t = 0; t < 11; t++) a11[t] = s.cb2[c2];
#pragma unroll
      for (int ci = 0; ci < 16; ci++) {
        const float4* mr = reinterpret_cast<const float4*>(mpsb + ci * 16);
        float4 A = mr[0], B = mr[1], C = mr[2], D = mr[3];
        float m[16] = {A.x,A.y,A.z,A.w, B.x,B.y,B.z,B.w, C.x,C.y,C.z,C.w, D.x,D.y,D.z,D.w};
#pragma unroll
        for (int q = 0; q < 5; q++) {
          float wv = s.cw2t[ci][q][c2];
#pragma unroll
          for (int t = 0; t < 11; t++) a11[t] = fmaf(wv, m[t + q], a11[t]);
        }
      }
#pragma unroll
      for (int t = 0; t < 11; t++) c2sb[c2 * 11 + t] = fmaxf(a11[t], 0.f);
    }
    __syncwarp();

    // ---- FC 352 -> 2 ----
    {
      float s0 = 0.f, s1 = 0.f;
#pragma unroll
      for (int j = 0; j < 11; j++) {
        int i = lane + 32 * j;
        float c = c2sb[i];
        s0 = fmaf(s.Wo[i], c, s0);
        s1 = fmaf(s.Wo[352 + i], c, s1);
      }
#pragma unroll
      for (int d = 16; d > 0; d >>= 1) {
        s0 += __shfl_xor_sync(0xffffffffu, s0, d);
        s1 += __shfl_xor_sync(0xffffffffu, s1, d);
      }
      if (lane == 0) {
        out[g * 2 + 0] = s0 + s.bo2[0];
        out[g * 2 + 1] = s1 + s.bo2[1];
      }
    }
    __syncwarp();
  }
}

extern "C" void kernel_launch(void* const* d_in, const int* in_sizes, int n_in,
                              void* d_out, int out_size) {
  const float* x   = (const float*)d_in[0];
  // d_in[1] = edge_index (unused by reference), d_in[2] = batch (i // (N/G))
  const float* W1  = (const float*)d_in[3];
  const float* b1  = (const float*)d_in[4];
  const float* W2  = (const float*)d_in[5];
  const float* b2  = (const float*)d_in[6];
  const float* W3  = (const float*)d_in[7];
  const float* b3  = (const float*)d_in[8];
  const float* W4  = (const float*)d_in[9];
  const float* b4  = (const float*)d_in[10];
  const float* cw1 = (const float*)d_in[11];
  const float* cb1 = (const float*)d_in[12];
  const float* cw2 = (const float*)d_in[13];
  const float* cb2 = (const float*)d_in[14];
  const float* Wo  = (const float*)d_in[15];
  const float* bo  = (const float*)d_in[16];
  float* out = (float*)d_out;

  int G = out_size / 2;       // 10000
  int N = in_sizes[0] / 64;   // 1000000
  int P = N / G;              // 100

  int smem = (int)sizeof(Smem);
  cudaFuncSetAttribute(dgcnn_kernel, cudaFuncAttributeMaxDynamicSharedMemorySize, smem);

  dgcnn_kernel<<<GRID, THREADS, smem>>>(x, W1, b1, W2, b2, W3, b3, W4, b4,
                                        cw1, cb1, cw2, cb2, Wo, bo, out, G, P);
}

// round 10
// speedup vs baseline: 1.0395x; 1.0395x over previous
#include <cuda_runtime.h>
#include <cstdint>

#define THREADS 256
#define NW 8            // warps per block; warp = one group
#define GRID 152

typedef unsigned long long ull;

__device__ __forceinline__ ull pk2(float lo, float hi) {
  ull r; asm("mov.b64 %0, {%1, %2};" : "=l"(r) : "f"(lo), "f"(hi)); return r;
}
__device__ __forceinline__ void unpk2(ull v, float& lo, float& hi) {
  asm("mov.b64 {%0, %1}, %2;" : "=f"(lo), "=f"(hi) : "l"(v));
}
__device__ __forceinline__ ull fma2(ull a, ull b, ull c) {
  ull d; asm("fma.rn.f32x2 %0, %1, %2, %3;" : "=l"(d) : "l"(a), "l"(b), "l"(c)); return d;
}

// ~100 KB dynamic shared memory. NO activation buffer — acts live in registers.
struct Smem {
  // All 4 layers (layer 4 zero-padded to 64 outs). Row k = 16 x 16B words;
  // logical feat-pair p (ol=p>>2, t=(p>>1)&1, u=p&1) stored at float2 slot
  // 16t + 2ol + u. Lane ol reads ulonglong2 words [ol] (pairs 4ol,4ol+1) and
  // [8+ol] (pairs 4ol+2,4ol+3): per phase 8 consecutive words -> conflict-free.
  alignas(16) float2 Wp[4][64][32];
  alignas(16) float2 Bp[4][32];       // logical pair order; layer-4 padded 0
  float  cw1t[5][16];     // [q][c]
  float  cb1[16];
  float  cw2t[16][5][32]; // [ci][q][c2]
  float  cb2[32];
  float  Wo[704];
  float  bo2[2];
  alignas(16) float  pooled[NW][40];
  alignas(16) float  mps[NW][16][16];
  alignas(16) float  c2s[NW][352];
};

__global__ void __launch_bounds__(THREADS, 1) dgcnn_kernel(
    const float* __restrict__ x,
    const float* __restrict__ W1, const float* __restrict__ b1,
    const float* __restrict__ W2, const float* __restrict__ b2,
    const float* __restrict__ W3, const float* __restrict__ b3,
    const float* __restrict__ W4, const float* __restrict__ b4,
    const float* __restrict__ cw1, const float* __restrict__ cb1,
    const float* __restrict__ cw2, const float* __restrict__ cb2,
    const float* __restrict__ Wo, const float* __restrict__ bo,
    float* __restrict__ out, int G, int P)
{
  extern __shared__ __align__(16) char smem_raw[];
  Smem& sm = *reinterpret_cast<Smem*>(smem_raw);
  const int tid  = threadIdx.x;
  const int w    = tid >> 5;
  const int lane = tid & 31;

  // ---- Stage weights once per block ----
  for (int idx = tid; idx < 4 * 64 * 32; idx += THREADS) {
    int l = idx >> 11, rem = idx & 2047, k = rem >> 5, p = rem & 31;
    int ol = p >> 2, t = (p >> 1) & 1, u = p & 1;
    int slot = 16 * t + 2 * ol + u;
    int f0 = 2 * p, f1 = 2 * p + 1;
    float v0, v1;
    if (l == 0)      { v0 = W1[f0 * 64 + k]; v1 = W1[f1 * 64 + k]; }
    else if (l == 1) { v0 = W2[f0 * 64 + k]; v1 = W2[f1 * 64 + k]; }
    else if (l == 2) { v0 = W3[f0 * 64 + k]; v1 = W3[f1 * 64 + k]; }
    else {
      v0 = (f0 < 34) ? W4[f0 * 64 + k] : 0.f;
      v1 = (f1 < 34) ? W4[f1 * 64 + k] : 0.f;
    }
    sm.Wp[l][k][slot] = make_float2(v0, v1);
  }
  for (int idx = tid; idx < 4 * 32; idx += THREADS) {
    int l = idx >> 5, p = idx & 31;
    int f0 = 2 * p, f1 = 2 * p + 1;
    float v0, v1;
    if (l == 0)      { v0 = b1[f0]; v1 = b1[f1]; }
    else if (l == 1) { v0 = b2[f0]; v1 = b2[f1]; }
    else if (l == 2) { v0 = b3[f0]; v1 = b3[f1]; }
    else {
      v0 = (f0 < 34) ? b4[f0] : 0.f;
      v1 = (f1 < 34) ? b4[f1] : 0.f;
    }
    sm.Bp[l][p] = make_float2(v0, v1);
  }
  for (int i = tid; i < 80; i += THREADS) { int q = i >> 4, c = i & 15; sm.cw1t[q][c] = cw1[c * 5 + q]; }
  if (tid < 16)  sm.cb1[tid] = cb1[tid];
  for (int i = tid; i < 2560; i += THREADS) {
    int ci = i / 160, r = i % 160, q = r >> 5, c2 = r & 31;
    sm.cw2t[ci][q][c2] = cw2[(c2 * 16 + ci) * 5 + q];
  }
  if (tid < 32)  sm.cb2[tid] = cb2[tid];
  for (int i = tid; i < 704; i += THREADS) sm.Wo[i] = Wo[i];
  if (tid < 2)   sm.bo2[tid] = bo[tid];
  __syncthreads();

  const int kc = (P < 30) ? P : 30;
  const float inv = 1.f / (float)kc;
  const int nl = lane >> 3;        // node group: nodes 8nl..8nl+7
  const int ol = lane & 7;         // feat group: feats 8ol..8ol+7
  const int srcbase = lane & 24;   // owner lane base (same nl)

  for (int g = blockIdx.x * NW + w; g < G; g += GRID * NW) {
    // ---- Load this lane's 8 nodes x 8 feats of x into registers ----
    float s[8][8];
    const float* xg = x + (size_t)g * P * 64 + 8 * ol;
#pragma unroll
    for (int n = 0; n < 8; n++) {
      int node = 8 * nl + n;
      bool act = node < kc;
      const float4* xr = reinterpret_cast<const float4*>(xg + (size_t)node * 64);
      float4 v0 = act ? xr[0] : make_float4(0.f, 0.f, 0.f, 0.f);
      float4 v1 = act ? xr[1] : make_float4(0.f, 0.f, 0.f, 0.f);
      s[n][0] = v0.x; s[n][1] = v0.y; s[n][2] = v0.z; s[n][3] = v0.w;
      s[n][4] = v1.x; s[n][5] = v1.y; s[n][6] = v1.z; s[n][7] = v1.w;
    }

    // ---- 4 MLP layers, activations in registers, shfl distribution ----
#pragma unroll 1
    for (int l = 0; l < 4; l++) {
      const float2* Wl = &sm.Wp[l][0][0];
      ull acc[8][4];
#pragma unroll
      for (int p = 0; p < 4; p++) {
        float2 b = sm.Bp[l][4 * ol + p];
        ull bb = pk2(b.x, b.y);
#pragma unroll
        for (int n = 0; n < 8; n++) acc[n][p] = bb;
      }
#pragma unroll 1
      for (int kb = 0; kb < 8; kb++) {
        int src = srcbase | kb;
        const ulonglong2* rowb = reinterpret_cast<const ulonglong2*>(Wl + (kb * 8) * 32);
#pragma unroll
        for (int kk = 0; kk < 8; kk++) {
          ulonglong2 wa = rowb[kk * 16 + ol];
          ulonglong2 wb = rowb[kk * 16 + 8 + ol];
#pragma unroll
          for (int n = 0; n < 8; n++) {
            float a = __shfl_sync(0xffffffffu, s[n][kk], src);
            ull ad = pk2(a, a);
            acc[n][0] = fma2(ad, wa.x, acc[n][0]);
            acc[n][1] = fma2(ad, wa.y, acc[n][1]);
            acc[n][2] = fma2(ad, wb.x, acc[n][2]);
            acc[n][3] = fma2(ad, wb.y, acc[n][3]);
          }
        }
      }
      // relu -> state registers (feats 8ol+j)
#pragma unroll
      for (int n = 0; n < 8; n++) {
#pragma unroll
        for (int p = 0; p < 4; p++) {
          float e, o; unpk2(acc[n][p], e, o);
          s[n][2 * p]     = fmaxf(e, 0.f);
          s[n][2 * p + 1] = fmaxf(o, 0.f);
        }
      }
    }

    // ---- Pool: mean over first kc nodes (register sums + nl-butterfly) ----
    {
      float v[8];
#pragma unroll
      for (int j = 0; j < 8; j++) v[j] = 0.f;
#pragma unroll
      for (int n = 0; n < 8; n++) {
        if (8 * nl + n < kc) {
#pragma unroll
          for (int j = 0; j < 8; j++) v[j] += s[n][j];
        }
      }
#pragma unroll
      for (int j = 0; j < 8; j++) {
        v[j] += __shfl_xor_sync(0xffffffffu, v[j], 8);
        v[j] += __shfl_xor_sync(0xffffffffu, v[j], 16);
      }
      if (nl == 0) {
#pragma unroll
        for (int j = 0; j < 8; j++) {
          int f = 8 * ol + j;
          if (f < 34) sm.pooled[w][f] = v[j] * inv;
        }
      }
    }
    __syncwarp();

    // ---- conv1 (16ch,k=5 -> 30) + ReLU + maxpool2 -> mps[16][15] ----
    {
      int c = lane & 15, h = lane >> 4;
      float wq[5];
#pragma unroll
      for (int q = 0; q < 5; q++) wq[q] = sm.cw1t[q][c];
      float bc = sm.cb1[c];
#pragma unroll
      for (int sIdx = 0; sIdx < 15; sIdx++) {
        int t = 2 * sIdx + h;
        float a = bc;
#pragma unroll
        for (int q = 0; q < 5; q++) a = fmaf(wq[q], sm.pooled[w][t + q], a);
        a = fmaxf(a, 0.f);
        float mv = fmaxf(a, __shfl_xor_sync(0xffffffffu, a, 16));
        if (h == 0) sm.mps[w][c][sIdx] = mv;
      }
    }
    __syncwarp();

    // ---- conv2 (32ch,16in,k=5 -> 11) + ReLU ----
    {
      int c2 = lane;
      float a11[11];
#pragma unroll
      for (int t = 0; t < 11; t++) a11[t] = sm.cb2[c2];
#pragma unroll
      for (int ci = 0; ci < 16; ci++) {
        const float4* mr = reinterpret_cast<const float4*>(&sm.mps[w][ci][0]);
        float4 A = mr[0], B = mr[1], C = mr[2], D = mr[3];
        float m[16] = {A.x,A.y,A.z,A.w, B.x,B.y,B.z,B.w, C.x,C.y,C.z,C.w, D.x,D.y,D.z,D.w};
#pragma unroll
        for (int q = 0; q < 5; q++) {
          float wv = sm.cw2t[ci][q][c2];
#pragma unroll
          for (int t = 0; t < 11; t++) a11[t] = fmaf(wv, m[t + q], a11[t]);
        }
      }
#pragma unroll
      for (int t = 0; t < 11; t++) sm.c2s[w][c2 * 11 + t] = fmaxf(a11[t], 0.f);
    }
    __syncwarp();

    // ---- FC 352 -> 2 ----
    {
      float s0 = 0.f, s1 = 0.f;
#pragma unroll
      for (int j = 0; j < 11; j++) {
        int i = lane + 32 * j;
        float c = sm.c2s[w][i];
        s0 = fmaf(sm.Wo[i], c, s0);
        s1 = fmaf(sm.Wo[352 + i], c, s1);
      }
#pragma unroll
      for (int d = 16; d > 0; d >>= 1) {
        s0 += __shfl_xor_sync(0xffffffffu, s0, d);
        s1 += __shfl_xor_sync(0xffffffffu, s1, d);
      }
      if (lane == 0) {
        out[g * 2 + 0] = s0 + sm.bo2[0];
        out[g * 2 + 1] = s1 + sm.bo2[1];
      }
    }
    __syncwarp();
  }
}

extern "C" void kernel_launch(void* const* d_in, const int* in_sizes, int n_in,
                              void* d_out, int out_size) {
  const float* x   = (const float*)d_in[0];
  // d_in[1] = edge_index (unused by reference), d_in[2] = batch (i // (N/G))
  const float* W1  = (const float*)d_in[3];
  const float* b1  = (const float*)d_in[4];
  const float* W2  = (const float*)d_in[5];
  const float* b2  = (const float*)d_in[6];
  const float* W3  = (const float*)d_in[7];
  const float* b3  = (const float*)d_in[8];
  const float* W4  = (const float*)d_in[9];
  const float* b4  = (const float*)d_in[10];
  const float* cw1 = (const float*)d_in[11];
  const float* cb1 = (const float*)d_in[12];
  const float* cw2 = (const float*)d_in[13];
  const float* cb2 = (const float*)d_in[14];
  const float* Wo  = (const float*)d_in[15];
  const float* bo  = (const float*)d_in[16];
  float* out = (float*)d_out;

  int G = out_size / 2;       // 10000
  int N = in_sizes[0] / 64;   // 1000000
  int P = N / G;              // 100

  int smem = (int)sizeof(Smem);
  cudaFuncSetAttribute(dgcnn_kernel, cudaFuncAttributeMaxDynamicSharedMemorySize, smem);

  dgcnn_kernel<<<GRID, THREADS, smem>>>(x, W1, b1, W2, b2, W3, b3, W4, b4,
                                        cw1, cb1, cw2, cb2, Wo, bo, out, G, P);
}

// round 11
// speedup vs baseline: 1.2612x; 1.2133x over previous
#include <cuda_runtime.h>
#include <cstdint>

#define THREADS 320
#define NW 10
#define GRID 152

__device__ __forceinline__ unsigned f2tf32u(float f) {
  unsigned u; asm("cvt.rna.tf32.f32 %0, %1;" : "=r"(u) : "f"(f)); return u;
}
__device__ __forceinline__ float tf32f(float f) {
  unsigned u; asm("cvt.rna.tf32.f32 %0, %1;" : "=r"(u) : "f"(f)); return __uint_as_float(u);
}
__device__ __forceinline__ void mma8(float* d, const unsigned* a, unsigned b0, unsigned b1) {
  asm("mma.sync.aligned.m16n8k8.row.col.f32.tf32.tf32.f32 "
      "{%0,%1,%2,%3}, {%4,%5,%6,%7}, {%8,%9}, {%0,%1,%2,%3};"
      : "+f"(d[0]), "+f"(d[1]), "+f"(d[2]), "+f"(d[3])
      : "r"(a[0]), "r"(a[1]), "r"(a[2]), "r"(a[3]), "r"(b0), "r"(b1));
}

// ~166 KB dynamic shared memory, 1 block (10 warps) per SM.
// Weight fragments pre-converted to tf32 hi/lo and pre-swizzled so each lane
// does ONE LDS.64 per (kt,nt) fragment (256B contiguous per tile, conflict-free).
struct Smem {
  alignas(16) float2 Wf[2][3][2048];   // [hi/lo][layer][(kt*8+nt)*32+lane]
  alignas(16) float2 W4f[2][1280];     // layer 4 (NT=5): [(kt*5+nt)*32+lane]
  alignas(16) float2 Bf[3][256];       // bias frags [nt*32+lane] = (b[8nt+2t], b[8nt+2t+1])
  alignas(16) float2 B4f[160];
  float cw1t[5][16];      // [q][c]
  float cb1[16];
  float cw2t[16][5][32];  // [ci][q][c2]
  float cb2[32];
  float Wo[704];
  float bo2[2];
  alignas(16) float pooled[NW][40];
  alignas(16) float mps[NW][16][16];
  alignas(16) float c2s[NW][352];
};

// One MMA layer: D[2][NT] (16x8 f32 tiles) = relu-input A (2x8 tiles) x W^T + b.
// 3xTF32: D += Ah*Bh + Al*Bh + Ah*Bl.
template <int NT>
__device__ __forceinline__ void mma_layer(const float2* __restrict__ Wh,
                                          const float2* __restrict__ Wl,
                                          const float2* __restrict__ Bfr,
                                          float A[2][8][4], float D[2][8][4],
                                          int lane) {
#pragma unroll
  for (int nt = 0; nt < NT; nt++) {
    float2 bb = Bfr[nt * 32 + lane];
#pragma unroll
    for (int mt = 0; mt < 2; mt++) {
      D[mt][nt][0] = bb.x; D[mt][nt][1] = bb.y;
      D[mt][nt][2] = bb.x; D[mt][nt][3] = bb.y;
    }
  }
#pragma unroll
  for (int kt = 0; kt < 8; kt++) {
    unsigned Ah[2][4], Al[2][4];
#pragma unroll
    for (int mt = 0; mt < 2; mt++)
#pragma unroll
      for (int i = 0; i < 4; i++) {
        float a = A[mt][kt][i];
        unsigned h = f2tf32u(a);
        Ah[mt][i] = h;
        Al[mt][i] = f2tf32u(a - __uint_as_float(h));
      }
#pragma unroll
    for (int nt = 0; nt < NT; nt++) {
      float2 bh = Wh[(kt * NT + nt) * 32 + lane];
      float2 bl = Wl[(kt * NT + nt) * 32 + lane];
      unsigned bh0 = __float_as_uint(bh.x), bh1 = __float_as_uint(bh.y);
      unsigned bl0 = __float_as_uint(bl.x), bl1 = __float_as_uint(bl.y);
#pragma unroll
      for (int mt = 0; mt < 2; mt++) {
        mma8(D[mt][nt], Ah[mt], bh0, bh1);
        mma8(D[mt][nt], Al[mt], bh0, bh1);
        mma8(D[mt][nt], Ah[mt], bl0, bl1);
      }
    }
  }
}

__global__ void __launch_bounds__(THREADS, 1) dgcnn_kernel(
    const float* __restrict__ x,
    const float* __restrict__ W1, const float* __restrict__ b1,
    const float* __restrict__ W2, const float* __restrict__ b2,
    const float* __restrict__ W3, const float* __restrict__ b3,
    const float* __restrict__ W4, const float* __restrict__ b4,
    const float* __restrict__ cw1, const float* __restrict__ cb1,
    const float* __restrict__ cw2, const float* __restrict__ cb2,
    const float* __restrict__ Wo, const float* __restrict__ bo,
    float* __restrict__ out, int G, int P)
{
  extern __shared__ __align__(16) char smem_raw[];
  Smem& sm = *reinterpret_cast<Smem*>(smem_raw);
  const int tid  = threadIdx.x;
  const int w    = tid >> 5;
  const int lane = tid & 31;
  const int gq   = lane >> 2;   // MMA groupID (row)
  const int tq   = lane & 3;    // MMA threadID (col/k)

  // ---- Stage weight fragments (tf32 hi/lo, pre-swizzled) ----
  for (int idx = tid; idx < 2 * 3 * 2048; idx += THREADS) {
    int part = idx / 6144, r = idx % 6144;
    int l = r / 2048, q = r % 2048;
    int ktnt = q >> 5, ln = q & 31;
    int kt = ktnt >> 3, nt = ktnt & 7;
    int g = ln >> 2, t = ln & 3;
    int n = nt * 8 + g, k0 = kt * 8 + t;
    const float* Ws = (l == 0) ? W1 : (l == 1) ? W2 : W3;
    float w0 = Ws[n * 64 + k0], w1 = Ws[n * 64 + k0 + 4];
    float2 st;
    if (part == 0) st = make_float2(tf32f(w0), tf32f(w1));
    else           st = make_float2(tf32f(w0 - tf32f(w0)), tf32f(w1 - tf32f(w1)));
    sm.Wf[part][l][q] = st;
  }
  for (int idx = tid; idx < 2 * 1280; idx += THREADS) {
    int part = idx / 1280, q = idx % 1280;
    int ktnt = q >> 5, ln = q & 31;
    int kt = ktnt / 5, nt = ktnt % 5;
    int g = ln >> 2, t = ln & 3;
    int n = nt * 8 + g, k0 = kt * 8 + t;
    float w0 = (n < 34) ? W4[n * 64 + k0] : 0.f;
    float w1 = (n < 34) ? W4[n * 64 + k0 + 4] : 0.f;
    float2 st;
    if (part == 0) st = make_float2(tf32f(w0), tf32f(w1));
    else           st = make_float2(tf32f(w0 - tf32f(w0)), tf32f(w1 - tf32f(w1)));
    sm.W4f[part][q] = st;
  }
  for (int idx = tid; idx < 3 * 256; idx += THREADS) {
    int l = idx / 256, q = idx % 256;
    int nt = q >> 5, t = q & 3;
    const float* bs = (l == 0) ? b1 : (l == 1) ? b2 : b3;
    int f = nt * 8 + 2 * t;
    sm.Bf[l][q] = make_float2(bs[f], bs[f + 1]);
  }
  for (int idx = tid; idx < 160; idx += THREADS) {
    int nt = idx >> 5, t = idx & 3;
    int f = nt * 8 + 2 * t;
    sm.B4f[idx] = make_float2((f < 34) ? b4[f] : 0.f, (f + 1 < 34) ? b4[f + 1] : 0.f);
  }
  for (int i = tid; i < 80; i += THREADS) { int q = i >> 4, c = i & 15; sm.cw1t[q][c] = cw1[c * 5 + q]; }
  if (tid < 16)  sm.cb1[tid] = cb1[tid];
  for (int i = tid; i < 2560; i += THREADS) {
    int ci = i / 160, r = i % 160, q = r >> 5, c2 = r & 31;
    sm.cw2t[ci][q][c2] = cw2[(c2 * 16 + ci) * 5 + q];
  }
  if (tid < 32)  sm.cb2[tid] = cb2[tid];
  for (int i = tid; i < 704; i += THREADS) sm.Wo[i] = Wo[i];
  if (tid < 2)   sm.bo2[tid] = bo[tid];
  __syncthreads();

  const int kc = (P < 30) ? P : 30;
  const float inv = 1.f / (float)kc;
  const unsigned FULL = 0xffffffffu;

  for (int g = blockIdx.x * NW + w; g < G; g += GRID * NW) {
    // ---- Load x directly as A-fragments (rows clamped for safety) ----
    float A[2][8][4];
    float D[2][8][4];
    {
      const float* xg = x + (size_t)g * P * 64;
#pragma unroll
      for (int mt = 0; mt < 2; mt++) {
        int r0 = mt * 16 + gq, r1 = r0 + 8;
        if (r0 >= P) r0 = P - 1;
        if (r1 >= P) r1 = P - 1;
        const float* p0 = xg + r0 * 64;
        const float* p1 = xg + r1 * 64;
#pragma unroll
        for (int kt = 0; kt < 8; kt++) {
          int c0 = kt * 8 + tq;
          A[mt][kt][0] = p0[c0];
          A[mt][kt][1] = p1[c0];
          A[mt][kt][2] = p0[c0 + 4];
          A[mt][kt][3] = p1[c0 + 4];
        }
      }
    }

    // ---- Layers 1-3: MMA + relu + re-fragment (D-layout -> A-layout) ----
#pragma unroll 1
    for (int l = 0; l < 3; l++) {
      mma_layer<8>(sm.Wf[0][l], sm.Wf[1][l], sm.Bf[l], A, D, lane);
      int s0 = (lane & 28) | (tq >> 1);
      int s1 = s0 | 2;
      bool odd = (tq & 1) != 0;
#pragma unroll
      for (int mt = 0; mt < 2; mt++) {
#pragma unroll
        for (int nt = 0; nt < 8; nt++) {
          float c0 = fmaxf(D[mt][nt][0], 0.f), c1 = fmaxf(D[mt][nt][1], 0.f);
          float c2 = fmaxf(D[mt][nt][2], 0.f), c3 = fmaxf(D[mt][nt][3], 0.f);
          float v00 = __shfl_sync(FULL, c0, s0), v01 = __shfl_sync(FULL, c1, s0);
          float v02 = __shfl_sync(FULL, c2, s0), v03 = __shfl_sync(FULL, c3, s0);
          float w00 = __shfl_sync(FULL, c0, s1), w01 = __shfl_sync(FULL, c1, s1);
          float w02 = __shfl_sync(FULL, c2, s1), w03 = __shfl_sync(FULL, c3, s1);
          A[mt][nt][0] = odd ? v01 : v00;
          A[mt][nt][1] = odd ? v03 : v02;
          A[mt][nt][2] = odd ? w01 : w00;
          A[mt][nt][3] = odd ? w03 : w02;
        }
      }
    }

    // ---- Layer 4 (NT=5, 40 padded cols) + relu + masked mean-pool ----
    {
      mma_layer<5>(sm.W4f[0], sm.W4f[1], sm.B4f, A, D, lane);
      float m00 = (gq < kc) ? 1.f : 0.f;
      float m01 = (8 + gq < kc) ? 1.f : 0.f;
      float m10 = (16 + gq < kc) ? 1.f : 0.f;
      float m11 = (24 + gq < kc) ? 1.f : 0.f;
      float se[5], so[5];
#pragma unroll
      for (int nt = 0; nt < 5; nt++) {
        se[nt] = m00 * fmaxf(D[0][nt][0], 0.f) + m01 * fmaxf(D[0][nt][2], 0.f)
               + m10 * fmaxf(D[1][nt][0], 0.f) + m11 * fmaxf(D[1][nt][2], 0.f);
        so[nt] = m00 * fmaxf(D[0][nt][1], 0.f) + m01 * fmaxf(D[0][nt][3], 0.f)
               + m10 * fmaxf(D[1][nt][1], 0.f) + m11 * fmaxf(D[1][nt][3], 0.f);
      }
#pragma unroll
      for (int d = 4; d < 32; d <<= 1) {
#pragma unroll
        for (int nt = 0; nt < 5; nt++) {
          se[nt] += __shfl_xor_sync(FULL, se[nt], d);
          so[nt] += __shfl_xor_sync(FULL, so[nt], d);
        }
      }
      if (lane < 4) {   // g == 0 lanes; t = lane
#pragma unroll
        for (int nt = 0; nt < 5; nt++) {
          int f = nt * 8 + 2 * lane;
          if (f < 34)     sm.pooled[w][f]     = se[nt] * inv;
          if (f + 1 < 34) sm.pooled[w][f + 1] = so[nt] * inv;
        }
      }
    }
    __syncwarp();

    // ---- conv1 (16ch,k=5 -> 30) + ReLU + maxpool2 -> mps[16][15] ----
    {
      int c = lane & 15, h = lane >> 4;
      float wq[5];
#pragma unroll
      for (int q = 0; q < 5; q++) wq[q] = sm.cw1t[q][c];
      float bc = sm.cb1[c];
#pragma unroll
      for (int sIdx = 0; sIdx < 15; sIdx++) {
        int t = 2 * sIdx + h;
        float a = bc;
#pragma unroll
        for (int q = 0; q < 5; q++) a = fmaf(wq[q], sm.pooled[w][t + q], a);
        a = fmaxf(a, 0.f);
        float mv = fmaxf(a, __shfl_xor_sync(FULL, a, 16));
        if (h == 0) sm.mps[w][c][sIdx] = mv;
      }
    }
    __syncwarp();

    // ---- conv2 (32ch,16in,k=5 -> 11) + ReLU ----
    {
      int c2 = lane;
      float a11[11];
#pragma unroll
      for (int t = 0; t < 11; t++) a11[t] = sm.cb2[c2];
#pragma unroll
      for (int ci = 0; ci < 16; ci++) {
        const float4* mr = reinterpret_cast<const float4*>(&sm.mps[w][ci][0]);
        float4 Aq = mr[0], Bq = mr[1], Cq = mr[2], Dq = mr[3];
        float m[16] = {Aq.x,Aq.y,Aq.z,Aq.w, Bq.x,Bq.y,Bq.z,Bq.w,
                       Cq.x,Cq.y,Cq.z,Cq.w, Dq.x,Dq.y,Dq.z,Dq.w};
#pragma unroll
        for (int q = 0; q < 5; q++) {
          float wv = sm.cw2t[ci][q][c2];
#pragma unroll
          for (int t = 0; t < 11; t++) a11[t] = fmaf(wv, m[t + q], a11[t]);
        }
      }
#pragma unroll
      for (int t = 0; t < 11; t++) sm.c2s[w][c2 * 11 + t] = fmaxf(a11[t], 0.f);
    }
    __syncwarp();

    // ---- FC 352 -> 2 ----
    {
      float s0 = 0.f, s1 = 0.f;
#pragma unroll
      for (int j = 0; j < 11; j++) {
        int i = lane + 32 * j;
        float c = sm.c2s[w][i];
        s0 = fmaf(sm.Wo[i], c, s0);
        s1 = fmaf(sm.Wo[352 + i], c, s1);
      }
#pragma unroll
      for (int d = 16; d > 0; d >>= 1) {
        s0 += __shfl_xor_sync(FULL, s0, d);
        s1 += __shfl_xor_sync(FULL, s1, d);
      }
      if (lane == 0) {
        out[g * 2 + 0] = s0 + sm.bo2[0];
        out[g * 2 + 1] = s1 + sm.bo2[1];
      }
    }
    __syncwarp();
  }
}

extern "C" void kernel_launch(void* const* d_in, const int* in_sizes, int n_in,
                              void* d_out, int out_size) {
  const float* x   = (const float*)d_in[0];
  // d_in[1] = edge_index (unused by reference), d_in[2] = batch (i // (N/G))
  const float* W1  = (const float*)d_in[3];
  const float* b1  = (const float*)d_in[4];
  const float* W2  = (const float*)d_in[5];
  const float* b2  = (const float*)d_in[6];
  const float* W3  = (const float*)d_in[7];
  const float* b3  = (const float*)d_in[8];
  const float* W4  = (const float*)d_in[9];
  const float* b4  = (const float*)d_in[10];
  const float* cw1 = (const float*)d_in[11];
  const float* cb1 = (const float*)d_in[12];
  const float* cw2 = (const float*)d_in[13];
  const float* cb2 = (const float*)d_in[14];
  const float* Wo  = (const float*)d_in[15];
  const float* bo  = (const float*)d_in[16];
  float* out = (float*)d_out;

  int G = out_size / 2;       // 10000
  int N = in_sizes[0] / 64;   // 1000000
  int P = N / G;              // 100

  int smem = (int)sizeof(Smem);
  cudaFuncSetAttribute(dgcnn_kernel, cudaFuncAttributeMaxDynamicSharedMemorySize, smem);

  dgcnn_kernel<<<GRID, THREADS, smem>>>(x, W1, b1, W2, b2, W3, b3, W4, b4,
                                        cw1, cb1, cw2, cb2, Wo, bo, out, G, P);
}

// round 12
// speedup vs baseline: 1.4473x; 1.1476x over previous
#include <cuda_runtime.h>
#include <cstdint>

#define THREADS 384
#define NW 12
#define GRID 152

__device__ __forceinline__ unsigned f2tf32u(float f) {
  unsigned u; asm("cvt.rna.tf32.f32 %0, %1;" : "=r"(u) : "f"(f)); return u;
}
__device__ __forceinline__ float tf32f(float f) {
  unsigned u; asm("cvt.rna.tf32.f32 %0, %1;" : "=r"(u) : "f"(f)); return __uint_as_float(u);
}
__device__ __forceinline__ void mma8(float* d, const unsigned* a, unsigned b0, unsigned b1) {
  asm("mma.sync.aligned.m16n8k8.row.col.f32.tf32.tf32.f32 "
      "{%0,%1,%2,%3}, {%4,%5,%6,%7}, {%8,%9}, {%0,%1,%2,%3};"
      : "+f"(d[0]), "+f"(d[1]), "+f"(d[2]), "+f"(d[3])
      : "r"(a[0]), "r"(a[1]), "r"(a[2]), "r"(a[3]), "r"(b0), "r"(b1));
}

// ~167 KB dynamic shared memory, 1 block (12 warps) per SM.
// Weight fragments pre-converted to tf32 hi/lo and pre-swizzled so each lane
// does ONE LDS.64 per (kt,nt) fragment (256B contiguous per tile, conflict-free).
struct Smem {
  alignas(16) float2 Wf[2][3][2048];   // [hi/lo][layer][(kt*8+nt)*32+lane]
  alignas(16) float2 W4f[2][1280];     // layer 4 (NT=5): [(kt*5+nt)*32+lane]
  alignas(16) float2 Bf[3][256];       // bias frags [nt*32+lane] = (b[8nt+2t], b[8nt+2t+1])
  alignas(16) float2 B4f[160];
  float cw1t[5][16];      // [q][c]
  float cb1[16];
  float cw2t[16][5][32];  // [ci][q][c2]
  float cb2[32];
  float Wo[704];
  float bo2[2];
  alignas(16) float pooled[NW][40];
  alignas(16) float mps[NW][16][16];
  alignas(16) float c2s[NW][352];
};

// One MMA layer: D[2][NT] (16x8 f32 tiles) = A (2x8 tiles) x W^T + b.
// 3xTF32: D += Ah*Bh + Al*Bh + Ah*Bl.
template <int NT>
__device__ __forceinline__ void mma_layer(const float2* __restrict__ Wh,
                                          const float2* __restrict__ Wl,
                                          const float2* __restrict__ Bfr,
                                          float A[2][8][4], float D[2][8][4],
                                          int lane) {
#pragma unroll
  for (int nt = 0; nt < NT; nt++) {
    float2 bb = Bfr[nt * 32 + lane];
#pragma unroll
    for (int mt = 0; mt < 2; mt++) {
      D[mt][nt][0] = bb.x; D[mt][nt][1] = bb.y;
      D[mt][nt][2] = bb.x; D[mt][nt][3] = bb.y;
    }
  }
#pragma unroll
  for (int kt = 0; kt < 8; kt++) {
    unsigned Ah[2][4], Al[2][4];
#pragma unroll
    for (int mt = 0; mt < 2; mt++)
#pragma unroll
      for (int i = 0; i < 4; i++) {
        float a = A[mt][kt][i];
        unsigned h = f2tf32u(a);
        Ah[mt][i] = h;
        Al[mt][i] = f2tf32u(a - __uint_as_float(h));
      }
#pragma unroll
    for (int nt = 0; nt < NT; nt++) {
      float2 bh = Wh[(kt * NT + nt) * 32 + lane];
      float2 bl = Wl[(kt * NT + nt) * 32 + lane];
      unsigned bh0 = __float_as_uint(bh.x), bh1 = __float_as_uint(bh.y);
      unsigned bl0 = __float_as_uint(bl.x), bl1 = __float_as_uint(bl.y);
#pragma unroll
      for (int mt = 0; mt < 2; mt++) {
        mma8(D[mt][nt], Ah[mt], bh0, bh1);
        mma8(D[mt][nt], Al[mt], bh0, bh1);
        mma8(D[mt][nt], Ah[mt], bl0, bl1);
      }
    }
  }
}

__global__ void __launch_bounds__(THREADS, 1) dgcnn_kernel(
    const float* __restrict__ x,
    const float* __restrict__ W1, const float* __restrict__ b1,
    const float* __restrict__ W2, const float* __restrict__ b2,
    const float* __restrict__ W3, const float* __restrict__ b3,
    const float* __restrict__ W4, const float* __restrict__ b4,
    const float* __restrict__ cw1, const float* __restrict__ cb1,
    const float* __restrict__ cw2, const float* __restrict__ cb2,
    const float* __restrict__ Wo, const float* __restrict__ bo,
    float* __restrict__ out, int G, int P)
{
  extern __shared__ __align__(16) char smem_raw[];
  Smem& sm = *reinterpret_cast<Smem*>(smem_raw);
  const int tid  = threadIdx.x;
  const int w    = tid >> 5;
  const int lane = tid & 31;
  const int gq   = lane >> 2;   // MMA groupID (row)
  const int tq   = lane & 3;    // MMA threadID (col/k)

  // ---- Stage weight fragments (tf32 hi/lo, pre-swizzled) ----
  for (int idx = tid; idx < 2 * 3 * 2048; idx += THREADS) {
    int part = idx / 6144, r = idx % 6144;
    int l = r / 2048, q = r % 2048;
    int ktnt = q >> 5, ln = q & 31;
    int kt = ktnt >> 3, nt = ktnt & 7;
    int g = ln >> 2, t = ln & 3;
    int n = nt * 8 + g, k0 = kt * 8 + t;
    const float* Ws = (l == 0) ? W1 : (l == 1) ? W2 : W3;
    float w0 = Ws[n * 64 + k0], w1 = Ws[n * 64 + k0 + 4];
    float2 st;
    if (part == 0) st = make_float2(tf32f(w0), tf32f(w1));
    else           st = make_float2(tf32f(w0 - tf32f(w0)), tf32f(w1 - tf32f(w1)));
    sm.Wf[part][l][q] = st;
  }
  for (int idx = tid; idx < 2 * 1280; idx += THREADS) {
    int part = idx / 1280, q = idx % 1280;
    int ktnt = q >> 5, ln = q & 31;
    int kt = ktnt / 5, nt = ktnt % 5;
    int g = ln >> 2, t = ln & 3;
    int n = nt * 8 + g, k0 = kt * 8 + t;
    float w0 = (n < 34) ? W4[n * 64 + k0] : 0.f;
    float w1 = (n < 34) ? W4[n * 64 + k0 + 4] : 0.f;
    float2 st;
    if (part == 0) st = make_float2(tf32f(w0), tf32f(w1));
    else           st = make_float2(tf32f(w0 - tf32f(w0)), tf32f(w1 - tf32f(w1)));
    sm.W4f[part][q] = st;
  }
  for (int idx = tid; idx < 3 * 256; idx += THREADS) {
    int l = idx / 256, q = idx % 256;
    int nt = q >> 5, t = q & 3;
    const float* bs = (l == 0) ? b1 : (l == 1) ? b2 : b3;
    int f = nt * 8 + 2 * t;
    sm.Bf[l][q] = make_float2(bs[f], bs[f + 1]);
  }
  for (int idx = tid; idx < 160; idx += THREADS) {
    int nt = idx >> 5, t = idx & 3;
    int f = nt * 8 + 2 * t;
    sm.B4f[idx] = make_float2((f < 34) ? b4[f] : 0.f, (f + 1 < 34) ? b4[f + 1] : 0.f);
  }
  for (int i = tid; i < 80; i += THREADS) { int q = i >> 4, c = i & 15; sm.cw1t[q][c] = cw1[c * 5 + q]; }
  if (tid < 16)  sm.cb1[tid] = cb1[tid];
  for (int i = tid; i < 2560; i += THREADS) {
    int ci = i / 160, r = i % 160, q = r >> 5, c2 = r & 31;
    sm.cw2t[ci][q][c2] = cw2[(c2 * 16 + ci) * 5 + q];
  }
  if (tid < 32)  sm.cb2[tid] = cb2[tid];
  for (int i = tid; i < 704; i += THREADS) sm.Wo[i] = Wo[i];
  if (tid < 2)   sm.bo2[tid] = bo[tid];
  __syncthreads();

  const int kc = (P < 30) ? P : 30;
  const float inv = 1.f / (float)kc;
  const unsigned FULL = 0xffffffffu;

  for (int g = blockIdx.x * NW + w; g < G; g += GRID * NW) {
    // ---- Load x directly as A-fragments (rows clamped for safety) ----
    float A[2][8][4];
    float D[2][8][4];
    {
      const float* xg = x + (size_t)g * P * 64;
#pragma unroll
      for (int mt = 0; mt < 2; mt++) {
        int r0 = mt * 16 + gq, r1 = r0 + 8;
        if (r0 >= P) r0 = P - 1;
        if (r1 >= P) r1 = P - 1;
        const float* p0 = xg + r0 * 64;
        const float* p1 = xg + r1 * 64;
#pragma unroll
        for (int kt = 0; kt < 8; kt++) {
          int c0 = kt * 8 + tq;
          A[mt][kt][0] = p0[c0];
          A[mt][kt][1] = p1[c0];
          A[mt][kt][2] = p0[c0 + 4];
          A[mt][kt][3] = p1[c0 + 4];
        }
      }
    }

    // ---- Layers 1-3: MMA + relu + re-fragment (D-layout -> A-layout) ----
#pragma unroll 1
    for (int l = 0; l < 3; l++) {
      mma_layer<8>(sm.Wf[0][l], sm.Wf[1][l], sm.Bf[l], A, D, lane);
      int s0 = (lane & 28) | (tq >> 1);
      int s1 = s0 | 2;
      bool odd = (tq & 1) != 0;
#pragma unroll
      for (int mt = 0; mt < 2; mt++) {
#pragma unroll
        for (int nt = 0; nt < 8; nt++) {
          float c0 = fmaxf(D[mt][nt][0], 0.f), c1 = fmaxf(D[mt][nt][1], 0.f);
          float c2 = fmaxf(D[mt][nt][2], 0.f), c3 = fmaxf(D[mt][nt][3], 0.f);
          float v00 = __shfl_sync(FULL, c0, s0), v01 = __shfl_sync(FULL, c1, s0);
          float v02 = __shfl_sync(FULL, c2, s0), v03 = __shfl_sync(FULL, c3, s0);
          float w00 = __shfl_sync(FULL, c0, s1), w01 = __shfl_sync(FULL, c1, s1);
          float w02 = __shfl_sync(FULL, c2, s1), w03 = __shfl_sync(FULL, c3, s1);
          A[mt][nt][0] = odd ? v01 : v00;
          A[mt][nt][1] = odd ? v03 : v02;
          A[mt][nt][2] = odd ? w01 : w00;
          A[mt][nt][3] = odd ? w03 : w02;
        }
      }
    }

    // ---- Layer 4 (NT=5, 40 padded cols) + relu + masked mean-pool ----
    {
      mma_layer<5>(sm.W4f[0], sm.W4f[1], sm.B4f, A, D, lane);
      float m00 = (gq < kc) ? 1.f : 0.f;
      float m01 = (8 + gq < kc) ? 1.f : 0.f;
      float m10 = (16 + gq < kc) ? 1.f : 0.f;
      float m11 = (24 + gq < kc) ? 1.f : 0.f;
      float se[5], so[5];
#pragma unroll
      for (int nt = 0; nt < 5; nt++) {
        se[nt] = m00 * fmaxf(D[0][nt][0], 0.f) + m01 * fmaxf(D[0][nt][2], 0.f)
               + m10 * fmaxf(D[1][nt][0], 0.f) + m11 * fmaxf(D[1][nt][2], 0.f);
        so[nt] = m00 * fmaxf(D[0][nt][1], 0.f) + m01 * fmaxf(D[0][nt][3], 0.f)
               + m10 * fmaxf(D[1][nt][1], 0.f) + m11 * fmaxf(D[1][nt][3], 0.f);
      }
#pragma unroll
      for (int d = 4; d < 32; d <<= 1) {
#pragma unroll
        for (int nt = 0; nt < 5; nt++) {
          se[nt] += __shfl_xor_sync(FULL, se[nt], d);
          so[nt] += __shfl_xor_sync(FULL, so[nt], d);
        }
      }
      if (lane < 4) {   // g == 0 lanes; t = lane
#pragma unroll
        for (int nt = 0; nt < 5; nt++) {
          int f = nt * 8 + 2 * lane;
          if (f < 34)     sm.pooled[w][f]     = se[nt] * inv;
          if (f + 1 < 34) sm.pooled[w][f + 1] = so[nt] * inv;
        }
      }
    }
    __syncwarp();

    // ---- conv1 (16ch,k=5 -> 30) + ReLU + maxpool2 -> mps[16][15] ----
    {
      int c = lane & 15, h = lane >> 4;
      float wq[5];
#pragma unroll
      for (int q = 0; q < 5; q++) wq[q] = sm.cw1t[q][c];
      float bc = sm.cb1[c];
#pragma unroll
      for (int sIdx = 0; sIdx < 15; sIdx++) {
        int t = 2 * sIdx + h;
        float a = bc;
#pragma unroll
        for (int q = 0; q < 5; q++) a = fmaf(wq[q], sm.pooled[w][t + q], a);
        a = fmaxf(a, 0.f);
        float mv = fmaxf(a, __shfl_xor_sync(FULL, a, 16));
        if (h == 0) sm.mps[w][c][sIdx] = mv;
      }
    }
    __syncwarp();

    // ---- conv2 (32ch,16in,k=5 -> 11) + ReLU ----
    {
      int c2 = lane;
      float a11[11];
#pragma unroll
      for (int t = 0; t < 11; t++) a11[t] = sm.cb2[c2];
#pragma unroll
      for (int ci = 0; ci < 16; ci++) {
        const float4* mr = reinterpret_cast<const float4*>(&sm.mps[w][ci][0]);
        float4 Aq = mr[0], Bq = mr[1], Cq = mr[2], Dq = mr[3];
        float m[16] = {Aq.x,Aq.y,Aq.z,Aq.w, Bq.x,Bq.y,Bq.z,Bq.w,
                       Cq.x,Cq.y,Cq.z,Cq.w, Dq.x,Dq.y,Dq.z,Dq.w};
#pragma unroll
        for (int q = 0; q < 5; q++) {
          float wv = sm.cw2t[ci][q][c2];
#pragma unroll
          for (int t = 0; t < 11; t++) a11[t] = fmaf(wv, m[t + q], a11[t]);
        }
      }
#pragma unroll
      for (int t = 0; t < 11; t++) sm.c2s[w][c2 * 11 + t] = fmaxf(a11[t], 0.f);
    }
    __syncwarp();

    // ---- FC 352 -> 2 ----
    {
      float s0 = 0.f, s1 = 0.f;
#pragma unroll
      for (int j = 0; j < 11; j++) {
        int i = lane + 32 * j;
        float c = sm.c2s[w][i];
        s0 = fmaf(sm.Wo[i], c, s0);
        s1 = fmaf(sm.Wo[352 + i], c, s1);
      }
#pragma unroll
      for (int d = 16; d > 0; d >>= 1) {
        s0 += __shfl_xor_sync(FULL, s0, d);
        s1 += __shfl_xor_sync(FULL, s1, d);
      }
      if (lane == 0) {
        out[g * 2 + 0] = s0 + sm.bo2[0];
        out[g * 2 + 1] = s1 + sm.bo2[1];
      }
    }
    __syncwarp();
  }
}

extern "C" void kernel_launch(void* const* d_in, const int* in_sizes, int n_in,
                              void* d_out, int out_size) {
  const float* x   = (const float*)d_in[0];
  // d_in[1] = edge_index (unused by reference), d_in[2] = batch (i // (N/G))
  const float* W1  = (const float*)d_in[3];
  const float* b1  = (const float*)d_in[4];
  const float* W2  = (const float*)d_in[5];
  const float* b2  = (const float*)d_in[6];
  const float* W3  = (const float*)d_in[7];
  const float* b3  = (const float*)d_in[8];
  const float* W4  = (const float*)d_in[9];
  const float* b4  = (const float*)d_in[10];
  const float* cw1 = (const float*)d_in[11];
  const float* cb1 = (const float*)d_in[12];
  const float* cw2 = (const float*)d_in[13];
  const float* cb2 = (const float*)d_in[14];
  const float* Wo  = (const float*)d_in[15];
  const float* bo  = (const float*)d_in[16];
  float* out = (float*)d_out;

  int G = out_size / 2;       // 10000
  int N = in_sizes[0] / 64;   // 1000000
  int P = N / G;              // 100

  int smem = (int)sizeof(Smem);
  cudaFuncSetAttribute(dgcnn_kernel, cudaFuncAttributeMaxDynamicSharedMemorySize, smem);

  dgcnn_kernel<<<GRID, THREADS, smem>>>(x, W1, b1, W2, b2, W3, b3, W4, b4,
                                        cw1, cb1, cw2, cb2, Wo, bo, out, G, P);
}

// round 13
// speedup vs baseline: 1.8313x; 1.2653x over previous
#include <cuda_runtime.h>
#include <cstdint>

#define THREADS 384
#define NW 12
#define GRID 152

__device__ __forceinline__ unsigned f2tf32u(float f) {
  unsigned u; asm("cvt.rna.tf32.f32 %0, %1;" : "=r"(u) : "f"(f)); return u;
}
__device__ __forceinline__ float tf32f(float f) {
  unsigned u; asm("cvt.rna.tf32.f32 %0, %1;" : "=r"(u) : "f"(f)); return __uint_as_float(u);
}
__device__ __forceinline__ void mma8(float* d, const unsigned* a, unsigned b0, unsigned b1) {
  asm("mma.sync.aligned.m16n8k8.row.col.f32.tf32.tf32.f32 "
      "{%0,%1,%2,%3}, {%4,%5,%6,%7}, {%8,%9}, {%0,%1,%2,%3};"
      : "+f"(d[0]), "+f"(d[1]), "+f"(d[2]), "+f"(d[3])
      : "r"(a[0]), "r"(a[1]), "r"(a[2]), "r"(a[3]), "r"(b0), "r"(b1));
}

// ~110 KB dynamic shared memory, 1 block (12 warps) per SM.
// 2xTF32: weights stored hi-only (tf32-rounded). A split into hi+lo:
// D = Ah*Bh + Al*Bh. Weight rounding error (~1e-4 rel) accepted vs 1e-3 gate.
struct Smem {
  alignas(16) float2 Wf[3][2048];   // [layer][(kt*8+nt)*32+lane] tf32 hi
  alignas(16) float2 W4f[1280];     // layer 4 (NT=5)
  alignas(16) float2 Bf[3][256];    // bias frags [nt*32+lane]
  alignas(16) float2 B4f[160];
  float cw1t[5][16];      // [q][c]
  float cb1[16];
  float cw2t[16][5][32];  // [ci][q][c2]
  float cb2[32];
  float Wo[704];
  float bo2[2];
  alignas(16) float pooled[NW][40];
  alignas(16) float mps[NW][16][16];
  alignas(16) float c2s[NW][352];
};

// One MMA layer: D[2][NT] (16x8 f32 tiles) = A (2x8 tiles) x W^T + b.
// 2xTF32: D += Ah*Bh + Al*Bh.
template <int NT>
__device__ __forceinline__ void mma_layer(const float2* __restrict__ Wh,
                                          const float2* __restrict__ Bfr,
                                          float A[2][8][4], float D[2][8][4],
                                          int lane) {
#pragma unroll
  for (int nt = 0; nt < NT; nt++) {
    float2 bb = Bfr[nt * 32 + lane];
#pragma unroll
    for (int mt = 0; mt < 2; mt++) {
      D[mt][nt][0] = bb.x; D[mt][nt][1] = bb.y;
      D[mt][nt][2] = bb.x; D[mt][nt][3] = bb.y;
    }
  }
#pragma unroll
  for (int kt = 0; kt < 8; kt++) {
    unsigned Ah[2][4], Al[2][4];
#pragma unroll
    for (int mt = 0; mt < 2; mt++)
#pragma unroll
      for (int i = 0; i < 4; i++) {
        float a = A[mt][kt][i];
        unsigned h = f2tf32u(a);
        Ah[mt][i] = h;
        Al[mt][i] = f2tf32u(a - __uint_as_float(h));
      }
#pragma unroll
    for (int nt = 0; nt < NT; nt++) {
      float2 bh = Wh[(kt * NT + nt) * 32 + lane];
      unsigned bh0 = __float_as_uint(bh.x), bh1 = __float_as_uint(bh.y);
#pragma unroll
      for (int mt = 0; mt < 2; mt++) {
        mma8(D[mt][nt], Ah[mt], bh0, bh1);
        mma8(D[mt][nt], Al[mt], bh0, bh1);
      }
    }
  }
}

__global__ void __launch_bounds__(THREADS, 1) dgcnn_kernel(
    const float* __restrict__ x,
    const float* __restrict__ W1, const float* __restrict__ b1,
    const float* __restrict__ W2, const float* __restrict__ b2,
    const float* __restrict__ W3, const float* __restrict__ b3,
    const float* __restrict__ W4, const float* __restrict__ b4,
    const float* __restrict__ cw1, const float* __restrict__ cb1,
    const float* __restrict__ cw2, const float* __restrict__ cb2,
    const float* __restrict__ Wo, const float* __restrict__ bo,
    float* __restrict__ out, int G, int P)
{
  extern __shared__ __align__(16) char smem_raw[];
  Smem& sm = *reinterpret_cast<Smem*>(smem_raw);
  const int tid  = threadIdx.x;
  const int w    = tid >> 5;
  const int lane = tid & 31;
  const int gq   = lane >> 2;   // MMA groupID (row)
  const int tq   = lane & 3;    // MMA threadID (col/k)

  // ---- Stage weight fragments (tf32 hi, pre-swizzled) ----
  for (int idx = tid; idx < 3 * 2048; idx += THREADS) {
    int l = idx / 2048, q = idx % 2048;
    int ktnt = q >> 5, ln = q & 31;
    int kt = ktnt >> 3, nt = ktnt & 7;
    int g = ln >> 2, t = ln & 3;
    int n = nt * 8 + g, k0 = kt * 8 + t;
    const float* Ws = (l == 0) ? W1 : (l == 1) ? W2 : W3;
    sm.Wf[l][q] = make_float2(tf32f(Ws[n * 64 + k0]), tf32f(Ws[n * 64 + k0 + 4]));
  }
  for (int idx = tid; idx < 1280; idx += THREADS) {
    int ktnt = idx >> 5, ln = idx & 31;
    int kt = ktnt / 5, nt = ktnt % 5;
    int g = ln >> 2, t = ln & 3;
    int n = nt * 8 + g, k0 = kt * 8 + t;
    float w0 = (n < 34) ? W4[n * 64 + k0] : 0.f;
    float w1 = (n < 34) ? W4[n * 64 + k0 + 4] : 0.f;
    sm.W4f[idx] = make_float2(tf32f(w0), tf32f(w1));
  }
  for (int idx = tid; idx < 3 * 256; idx += THREADS) {
    int l = idx / 256, q = idx % 256;
    int nt = q >> 5, t = q & 3;
    const float* bs = (l == 0) ? b1 : (l == 1) ? b2 : b3;
    int f = nt * 8 + 2 * t;
    sm.Bf[l][q] = make_float2(bs[f], bs[f + 1]);
  }
  for (int idx = tid; idx < 160; idx += THREADS) {
    int nt = idx >> 5, t = idx & 3;
    int f = nt * 8 + 2 * t;
    sm.B4f[idx] = make_float2((f < 34) ? b4[f] : 0.f, (f + 1 < 34) ? b4[f + 1] : 0.f);
  }
  for (int i = tid; i < 80; i += THREADS) { int q = i >> 4, c = i & 15; sm.cw1t[q][c] = cw1[c * 5 + q]; }
  if (tid < 16)  sm.cb1[tid] = cb1[tid];
  for (int i = tid; i < 2560; i += THREADS) {
    int ci = i / 160, r = i % 160, q = r >> 5, c2 = r & 31;
    sm.cw2t[ci][q][c2] = cw2[(c2 * 16 + ci) * 5 + q];
  }
  if (tid < 32)  sm.cb2[tid] = cb2[tid];
  for (int i = tid; i < 704; i += THREADS) sm.Wo[i] = Wo[i];
  if (tid < 2)   sm.bo2[tid] = bo[tid];
  __syncthreads();

  const int kc = (P < 30) ? P : 30;
  const float inv = 1.f / (float)kc;
  const unsigned FULL = 0xffffffffu;

  for (int g = blockIdx.x * NW + w; g < G; g += GRID * NW) {
    // ---- Load x directly as A-fragments (rows clamped for safety) ----
    float A[2][8][4];
    float D[2][8][4];
    {
      const float* xg = x + (size_t)g * P * 64;
#pragma unroll
      for (int mt = 0; mt < 2; mt++) {
        int r0 = mt * 16 + gq, r1 = r0 + 8;
        if (r0 >= P) r0 = P - 1;
        if (r1 >= P) r1 = P - 1;
        const float* p0 = xg + r0 * 64;
        const float* p1 = xg + r1 * 64;
#pragma unroll
        for (int kt = 0; kt < 8; kt++) {
          int c0 = kt * 8 + tq;
          A[mt][kt][0] = p0[c0];
          A[mt][kt][1] = p1[c0];
          A[mt][kt][2] = p0[c0 + 4];
          A[mt][kt][3] = p1[c0 + 4];
        }
      }
    }

    // ---- Layers 1-3: MMA + relu + re-fragment (D-layout -> A-layout) ----
#pragma unroll 1
    for (int l = 0; l < 3; l++) {
      mma_layer<8>(sm.Wf[l], sm.Bf[l], A, D, lane);
      int s0 = (lane & 28) | (tq >> 1);
      int s1 = s0 | 2;
      bool odd = (tq & 1) != 0;
#pragma unroll
      for (int mt = 0; mt < 2; mt++) {
#pragma unroll
        for (int nt = 0; nt < 8; nt++) {
          float c0 = fmaxf(D[mt][nt][0], 0.f), c1 = fmaxf(D[mt][nt][1], 0.f);
          float c2 = fmaxf(D[mt][nt][2], 0.f), c3 = fmaxf(D[mt][nt][3], 0.f);
          float v00 = __shfl_sync(FULL, c0, s0), v01 = __shfl_sync(FULL, c1, s0);
          float v02 = __shfl_sync(FULL, c2, s0), v03 = __shfl_sync(FULL, c3, s0);
          float w00 = __shfl_sync(FULL, c0, s1), w01 = __shfl_sync(FULL, c1, s1);
          float w02 = __shfl_sync(FULL, c2, s1), w03 = __shfl_sync(FULL, c3, s1);
          A[mt][nt][0] = odd ? v01 : v00;
          A[mt][nt][1] = odd ? v03 : v02;
          A[mt][nt][2] = odd ? w01 : w00;
          A[mt][nt][3] = odd ? w03 : w02;
        }
      }
    }

    // ---- Layer 4 (NT=5, 40 padded cols) + relu + masked mean-pool ----
    {
      mma_layer<5>(sm.W4f, sm.B4f, A, D, lane);
      float m00 = (gq < kc) ? 1.f : 0.f;
      float m01 = (8 + gq < kc) ? 1.f : 0.f;
      float m10 = (16 + gq < kc) ? 1.f : 0.f;
      float m11 = (24 + gq < kc) ? 1.f : 0.f;
      float se[5], so[5];
#pragma unroll
      for (int nt = 0; nt < 5; nt++) {
        se[nt] = m00 * fmaxf(D[0][nt][0], 0.f) + m01 * fmaxf(D[0][nt][2], 0.f)
               + m10 * fmaxf(D[1][nt][0], 0.f) + m11 * fmaxf(D[1][nt][2], 0.f);
        so[nt] = m00 * fmaxf(D[0][nt][1], 0.f) + m01 * fmaxf(D[0][nt][3], 0.f)
               + m10 * fmaxf(D[1][nt][1], 0.f) + m11 * fmaxf(D[1][nt][3], 0.f);
      }
#pragma unroll
      for (int d = 4; d < 32; d <<= 1) {
#pragma unroll
        for (int nt = 0; nt < 5; nt++) {
          se[nt] += __shfl_xor_sync(FULL, se[nt], d);
          so[nt] += __shfl_xor_sync(FULL, so[nt], d);
        }
      }
      if (lane < 4) {   // g == 0 lanes; t = lane
#pragma unroll
        for (int nt = 0; nt < 5; nt++) {
          int f = nt * 8 + 2 * lane;
          if (f < 34)     sm.pooled[w][f]     = se[nt] * inv;
          if (f + 1 < 34) sm.pooled[w][f + 1] = so[nt] * inv;
        }
      }
    }
    __syncwarp();

    // ---- conv1 (16ch,k=5 -> 30) + ReLU + maxpool2 -> mps[16][15] ----
    {
      int c = lane & 15, h = lane >> 4;
      float wq[5];
#pragma unroll
      for (int q = 0; q < 5; q++) wq[q] = sm.cw1t[q][c];
      float bc = sm.cb1[c];
#pragma unroll
      for (int sIdx = 0; sIdx < 15; sIdx++) {
        int t = 2 * sIdx + h;
        float a = bc;
#pragma unroll
        for (int q = 0; q < 5; q++) a = fmaf(wq[q], sm.pooled[w][t + q], a);
        a = fmaxf(a, 0.f);
        float mv = fmaxf(a, __shfl_xor_sync(FULL, a, 16));
        if (h == 0) sm.mps[w][c][sIdx] = mv;
      }
    }
    __syncwarp();

    // ---- conv2 (32ch,16in,k=5 -> 11) + ReLU ----
    {
      int c2 = lane;
      float a11[11];
#pragma unroll
      for (int t = 0; t < 11; t++) a11[t] = sm.cb2[c2];
#pragma unroll
      for (int ci = 0; ci < 16; ci++) {
        const float4* mr = reinterpret_cast<const float4*>(&sm.mps[w][ci][0]);
        float4 Aq = mr[0], Bq = mr[1], Cq = mr[2], Dq = mr[3];
        float m[16] = {Aq.x,Aq.y,Aq.z,Aq.w, Bq.x,Bq.y,Bq.z,Bq.w,
                       Cq.x,Cq.y,Cq.z,Cq.w, Dq.x,Dq.y,Dq.z,Dq.w};
#pragma unroll
        for (int q = 0; q < 5; q++) {
          float wv = sm.cw2t[ci][q][c2];
#pragma unroll
          for (int t = 0; t < 11; t++) a11[t] = fmaf(wv, m[t + q], a11[t]);
        }
      }
#pragma unroll
      for (int t = 0; t < 11; t++) sm.c2s[w][c2 * 11 + t] = fmaxf(a11[t], 0.f);
    }
    __syncwarp();

    // ---- FC 352 -> 2 ----
    {
      float s0 = 0.f, s1 = 0.f;
#pragma unroll
      for (int j = 0; j < 11; j++) {
        int i = lane + 32 * j;
        float c = sm.c2s[w][i];
        s0 = fmaf(sm.Wo[i], c, s0);
        s1 = fmaf(sm.Wo[352 + i], c, s1);
      }
#pragma unroll
      for (int d = 16; d > 0; d >>= 1) {
        s0 += __shfl_xor_sync(FULL, s0, d);
        s1 += __shfl_xor_sync(FULL, s1, d);
      }
      if (lane == 0) {
        out[g * 2 + 0] = s0 + sm.bo2[0];
        out[g * 2 + 1] = s1 + sm.bo2[1];
      }
    }
    __syncwarp();
  }
}

extern "C" void kernel_launch(void* const* d_in, const int* in_sizes, int n_in,
                              void* d_out, int out_size) {
  const float* x   = (const float*)d_in[0];
  // d_in[1] = edge_index (unused by reference), d_in[2] = batch (i // (N/G))
  const float* W1  = (const float*)d_in[3];
  const float* b1  = (const float*)d_in[4];
  const float* W2  = (const float*)d_in[5];
  const float* b2  = (const float*)d_in[6];
  const float* W3  = (const float*)d_in[7];
  const float* b3  = (const float*)d_in[8];
  const float* W4  = (const float*)d_in[9];
  const float* b4  = (const float*)d_in[10];
  const float* cw1 = (const float*)d_in[11];
  const float* cb1 = (const float*)d_in[12];
  const float* cw2 = (const float*)d_in[13];
  const float* cb2 = (const float*)d_in[14];
  const float* Wo  = (const float*)d_in[15];
  const float* bo  = (const float*)d_in[16];
  float* out = (float*)d_out;

  int G = out_size / 2;       // 10000
  int N = in_sizes[0] / 64;   // 1000000
  int P = N / G;              // 100

  int smem = (int)sizeof(Smem);
  cudaFuncSetAttribute(dgcnn_kernel, cudaFuncAttributeMaxDynamicSharedMemorySize, smem);

  dgcnn_kernel<<<GRID, THREADS, smem>>>(x, W1, b1, W2, b2, W3, b3, W4, b4,
                                        cw1, cb1, cw2, cb2, Wo, bo, out, G, P);
}

// round 14
// speedup vs baseline: 2.5674x; 1.4020x over previous
#include <cuda_runtime.h>
#include <cstdint>

#define THREADS 384
#define NW 12
#define GRID 152

__device__ __forceinline__ unsigned f2tf32u(float f) {
  unsigned u; asm("cvt.rna.tf32.f32 %0, %1;" : "=r"(u) : "f"(f)); return u;
}
__device__ __forceinline__ float tf32f(float f) {
  unsigned u; asm("cvt.rna.tf32.f32 %0, %1;" : "=r"(u) : "f"(f)); return __uint_as_float(u);
}
__device__ __forceinline__ void mma8(float* d, const unsigned* a, unsigned b0, unsigned b1) {
  asm("mma.sync.aligned.m16n8k8.row.col.f32.tf32.tf32.f32 "
      "{%0,%1,%2,%3}, {%4,%5,%6,%7}, {%8,%9}, {%0,%1,%2,%3};"
      : "+f"(d[0]), "+f"(d[1]), "+f"(d[2]), "+f"(d[3])
      : "r"(a[0]), "r"(a[1]), "r"(a[2]), "r"(a[3]), "r"(b0), "r"(b1));
}

// ~110 KB dynamic shared memory, 1 block (12 warps) per SM.
// 1xTF32: weights AND activations tf32-rounded (rna). Measured 2x error was
// 1.6e-4 (3x better than worst-case u); same scaling puts 1x at ~3-6e-4 < 1e-3.
struct Smem {
  alignas(16) float2 Wf[3][2048];   // [layer][(kt*8+nt)*32+lane] tf32
  alignas(16) float2 W4f[1280];     // layer 4 (NT=5)
  alignas(16) float2 Bf[3][256];    // bias frags [nt*32+lane]
  alignas(16) float2 B4f[160];
  float cw1t[5][16];      // [q][c]
  float cb1[16];
  float cw2t[16][5][32];  // [ci][q][c2]
  float cb2[32];
  float Wo[704];
  float bo2[2];
  alignas(16) float pooled[NW][40];
  alignas(16) float mps[NW][16][16];
  alignas(16) float c2s[NW][352];
};

// One MMA layer: D[2][NT] (16x8 f32 tiles) = A (2x8 tiles) x W^T + b. 1xTF32.
template <int NT>
__device__ __forceinline__ void mma_layer(const float2* __restrict__ Wh,
                                          const float2* __restrict__ Bfr,
                                          float A[2][8][4], float D[2][8][4],
                                          int lane) {
#pragma unroll
  for (int nt = 0; nt < NT; nt++) {
    float2 bb = Bfr[nt * 32 + lane];
#pragma unroll
    for (int mt = 0; mt < 2; mt++) {
      D[mt][nt][0] = bb.x; D[mt][nt][1] = bb.y;
      D[mt][nt][2] = bb.x; D[mt][nt][3] = bb.y;
    }
  }
#pragma unroll
  for (int kt = 0; kt < 8; kt++) {
    unsigned Ah[2][4];
#pragma unroll
    for (int mt = 0; mt < 2; mt++)
#pragma unroll
      for (int i = 0; i < 4; i++)
        Ah[mt][i] = f2tf32u(A[mt][kt][i]);
#pragma unroll
    for (int nt = 0; nt < NT; nt++) {
      float2 bh = Wh[(kt * NT + nt) * 32 + lane];
      unsigned bh0 = __float_as_uint(bh.x), bh1 = __float_as_uint(bh.y);
#pragma unroll
      for (int mt = 0; mt < 2; mt++)
        mma8(D[mt][nt], Ah[mt], bh0, bh1);
    }
  }
}

__global__ void __launch_bounds__(THREADS, 1) dgcnn_kernel(
    const float* __restrict__ x,
    const float* __restrict__ W1, const float* __restrict__ b1,
    const float* __restrict__ W2, const float* __restrict__ b2,
    const float* __restrict__ W3, const float* __restrict__ b3,
    const float* __restrict__ W4, const float* __restrict__ b4,
    const float* __restrict__ cw1, const float* __restrict__ cb1,
    const float* __restrict__ cw2, const float* __restrict__ cb2,
    const float* __restrict__ Wo, const float* __restrict__ bo,
    float* __restrict__ out, int G, int P)
{
  extern __shared__ __align__(16) char smem_raw[];
  Smem& sm = *reinterpret_cast<Smem*>(smem_raw);
  const int tid  = threadIdx.x;
  const int w    = tid >> 5;
  const int lane = tid & 31;
  const int gq   = lane >> 2;   // MMA groupID (row)
  const int tq   = lane & 3;    // MMA threadID (col/k)

  // ---- Stage weight fragments (tf32, pre-swizzled) ----
  for (int idx = tid; idx < 3 * 2048; idx += THREADS) {
    int l = idx / 2048, q = idx % 2048;
    int ktnt = q >> 5, ln = q & 31;
    int kt = ktnt >> 3, nt = ktnt & 7;
    int g = ln >> 2, t = ln & 3;
    int n = nt * 8 + g, k0 = kt * 8 + t;
    const float* Ws = (l == 0) ? W1 : (l == 1) ? W2 : W3;
    sm.Wf[l][q] = make_float2(tf32f(Ws[n * 64 + k0]), tf32f(Ws[n * 64 + k0 + 4]));
  }
  for (int idx = tid; idx < 1280; idx += THREADS) {
    int ktnt = idx >> 5, ln = idx & 31;
    int kt = ktnt / 5, nt = ktnt % 5;
    int g = ln >> 2, t = ln & 3;
    int n = nt * 8 + g, k0 = kt * 8 + t;
    float w0 = (n < 34) ? W4[n * 64 + k0] : 0.f;
    float w1 = (n < 34) ? W4[n * 64 + k0 + 4] : 0.f;
    sm.W4f[idx] = make_float2(tf32f(w0), tf32f(w1));
  }
  for (int idx = tid; idx < 3 * 256; idx += THREADS) {
    int l = idx / 256, q = idx % 256;
    int nt = q >> 5, t = q & 3;
    const float* bs = (l == 0) ? b1 : (l == 1) ? b2 : b3;
    int f = nt * 8 + 2 * t;
    sm.Bf[l][q] = make_float2(bs[f], bs[f + 1]);
  }
  for (int idx = tid; idx < 160; idx += THREADS) {
    int nt = idx >> 5, t = idx & 3;
    int f = nt * 8 + 2 * t;
    sm.B4f[idx] = make_float2((f < 34) ? b4[f] : 0.f, (f + 1 < 34) ? b4[f + 1] : 0.f);
  }
  for (int i = tid; i < 80; i += THREADS) { int q = i >> 4, c = i & 15; sm.cw1t[q][c] = cw1[c * 5 + q]; }
  if (tid < 16)  sm.cb1[tid] = cb1[tid];
  for (int i = tid; i < 2560; i += THREADS) {
    int ci = i / 160, r = i % 160, q = r >> 5, c2 = r & 31;
    sm.cw2t[ci][q][c2] = cw2[(c2 * 16 + ci) * 5 + q];
  }
  if (tid < 32)  sm.cb2[tid] = cb2[tid];
  for (int i = tid; i < 704; i += THREADS) sm.Wo[i] = Wo[i];
  if (tid < 2)   sm.bo2[tid] = bo[tid];
  __syncthreads();

  const int kc = (P < 30) ? P : 30;
  const float inv = 1.f / (float)kc;
  const unsigned FULL = 0xffffffffu;

  for (int g = blockIdx.x * NW + w; g < G; g += GRID * NW) {
    // ---- Load x directly as A-fragments (rows clamped for safety) ----
    float A[2][8][4];
    float D[2][8][4];
    {
      const float* xg = x + (size_t)g * P * 64;
#pragma unroll
      for (int mt = 0; mt < 2; mt++) {
        int r0 = mt * 16 + gq, r1 = r0 + 8;
        if (r0 >= P) r0 = P - 1;
        if (r1 >= P) r1 = P - 1;
        const float* p0 = xg + r0 * 64;
        const float* p1 = xg + r1 * 64;
#pragma unroll
        for (int kt = 0; kt < 8; kt++) {
          int c0 = kt * 8 + tq;
          A[mt][kt][0] = p0[c0];
          A[mt][kt][1] = p1[c0];
          A[mt][kt][2] = p0[c0 + 4];
          A[mt][kt][3] = p1[c0 + 4];
        }
      }
    }

    // ---- Layers 1-3: MMA + relu + re-fragment (D-layout -> A-layout) ----
#pragma unroll 1
    for (int l = 0; l < 3; l++) {
      mma_layer<8>(sm.Wf[l], sm.Bf[l], A, D, lane);
      int s0 = (lane & 28) | (tq >> 1);
      int s1 = s0 | 2;
      bool odd = (tq & 1) != 0;
#pragma unroll
      for (int mt = 0; mt < 2; mt++) {
#pragma unroll
        for (int nt = 0; nt < 8; nt++) {
          float c0 = fmaxf(D[mt][nt][0], 0.f), c1 = fmaxf(D[mt][nt][1], 0.f);
          float c2 = fmaxf(D[mt][nt][2], 0.f), c3 = fmaxf(D[mt][nt][3], 0.f);
          float v00 = __shfl_sync(FULL, c0, s0), v01 = __shfl_sync(FULL, c1, s0);
          float v02 = __shfl_sync(FULL, c2, s0), v03 = __shfl_sync(FULL, c3, s0);
          float w00 = __shfl_sync(FULL, c0, s1), w01 = __shfl_sync(FULL, c1, s1);
          float w02 = __shfl_sync(FULL, c2, s1), w03 = __shfl_sync(FULL, c3, s1);
          A[mt][nt][0] = odd ? v01 : v00;
          A[mt][nt][1] = odd ? v03 : v02;
          A[mt][nt][2] = odd ? w01 : w00;
          A[mt][nt][3] = odd ? w03 : w02;
        }
      }
    }

    // ---- Layer 4 (NT=5, 40 padded cols) + relu + masked mean-pool ----
    {
      mma_layer<5>(sm.W4f, sm.B4f, A, D, lane);
      float m00 = (gq < kc) ? 1.f : 0.f;
      float m01 = (8 + gq < kc) ? 1.f : 0.f;
      float m10 = (16 + gq < kc) ? 1.f : 0.f;
      float m11 = (24 + gq < kc) ? 1.f : 0.f;
      float se[5], so[5];
#pragma unroll
      for (int nt = 0; nt < 5; nt++) {
        se[nt] = m00 * fmaxf(D[0][nt][0], 0.f) + m01 * fmaxf(D[0][nt][2], 0.f)
               + m10 * fmaxf(D[1][nt][0], 0.f) + m11 * fmaxf(D[1][nt][2], 0.f);
        so[nt] = m00 * fmaxf(D[0][nt][1], 0.f) + m01 * fmaxf(D[0][nt][3], 0.f)
               + m10 * fmaxf(D[1][nt][1], 0.f) + m11 * fmaxf(D[1][nt][3], 0.f);
      }
#pragma unroll
      for (int d = 4; d < 32; d <<= 1) {
#pragma unroll
        for (int nt = 0; nt < 5; nt++) {
          se[nt] += __shfl_xor_sync(FULL, se[nt], d);
          so[nt] += __shfl_xor_sync(FULL, so[nt], d);
        }
      }
      if (lane < 4) {   // g == 0 lanes; t = lane
#pragma unroll
        for (int nt = 0; nt < 5; nt++) {
          int f = nt * 8 + 2 * lane;
          if (f < 34)     sm.pooled[w][f]     = se[nt] * inv;
          if (f + 1 < 34) sm.pooled[w][f + 1] = so[nt] * inv;
        }
      }
    }
    __syncwarp();

    // ---- conv1 (16ch,k=5 -> 30) + ReLU + maxpool2 -> mps[16][15] ----
    {
      int c = lane & 15, h = lane >> 4;
      float wq[5];
#pragma unroll
      for (int q = 0; q < 5; q++) wq[q] = sm.cw1t[q][c];
      float bc = sm.cb1[c];
#pragma unroll
      for (int sIdx = 0; sIdx < 15; sIdx++) {
        int t = 2 * sIdx + h;
        float a = bc;
#pragma unroll
        for (int q = 0; q < 5; q++) a = fmaf(wq[q], sm.pooled[w][t + q], a);
        a = fmaxf(a, 0.f);
        float mv = fmaxf(a, __shfl_xor_sync(FULL, a, 16));
        if (h == 0) sm.mps[w][c][sIdx] = mv;
      }
    }
    __syncwarp();

    // ---- conv2 (32ch,16in,k=5 -> 11) + ReLU ----
    {
      int c2 = lane;
      float a11[11];
#pragma unroll
      for (int t = 0; t < 11; t++) a11[t] = sm.cb2[c2];
#pragma unroll
      for (int ci = 0; ci < 16; ci++) {
        const float4* mr = reinterpret_cast<const float4*>(&sm.mps[w][ci][0]);
        float4 Aq = mr[0], Bq = mr[1], Cq = mr[2], Dq = mr[3];
        float m[16] = {Aq.x,Aq.y,Aq.z,Aq.w, Bq.x,Bq.y,Bq.z,Bq.w,
                       Cq.x,Cq.y,Cq.z,Cq.w, Dq.x,Dq.y,Dq.z,Dq.w};
#pragma unroll
        for (int q = 0; q < 5; q++) {
          float wv = sm.cw2t[ci][q][c2];
#pragma unroll
          for (int t = 0; t < 11; t++) a11[t] = fmaf(wv, m[t + q], a11[t]);
        }
      }
#pragma unroll
      for (int t = 0; t < 11; t++) sm.c2s[w][c2 * 11 + t] = fmaxf(a11[t], 0.f);
    }
    __syncwarp();

    // ---- FC 352 -> 2 ----
    {
      float s0 = 0.f, s1 = 0.f;
#pragma unroll
      for (int j = 0; j < 11; j++) {
        int i = lane + 32 * j;
        float c = sm.c2s[w][i];
        s0 = fmaf(sm.Wo[i], c, s0);
        s1 = fmaf(sm.Wo[352 + i], c, s1);
      }
#pragma unroll
      for (int d = 16; d > 0; d >>= 1) {
        s0 += __shfl_xor_sync(FULL, s0, d);
        s1 += __shfl_xor_sync(FULL, s1, d);
      }
      if (lane == 0) {
        out[g * 2 + 0] = s0 + sm.bo2[0];
        out[g * 2 + 1] = s1 + sm.bo2[1];
      }
    }
    __syncwarp();
  }
}

extern "C" void kernel_launch(void* const* d_in, const int* in_sizes, int n_in,
                              void* d_out, int out_size) {
  const float* x   = (const float*)d_in[0];
  // d_in[1] = edge_index (unused by reference), d_in[2] = batch (i // (N/G))
  const float* W1  = (const float*)d_in[3];
  const float* b1  = (const float*)d_in[4];
  const float* W2  = (const float*)d_in[5];
  const float* b2  = (const float*)d_in[6];
  const float* W3  = (const float*)d_in[7];
  const float* b3  = (const float*)d_in[8];
  const float* W4  = (const float*)d_in[9];
  const float* b4  = (const float*)d_in[10];
  const float* cw1 = (const float*)d_in[11];
  const float* cb1 = (const float*)d_in[12];
  const float* cw2 = (const float*)d_in[13];
  const float* cb2 = (const float*)d_in[14];
  const float* Wo  = (const float*)d_in[15];
  const float* bo  = (const float*)d_in[16];
  float* out = (float*)d_out;

  int G = out_size / 2;       // 10000
  int N = in_sizes[0] / 64;   // 1000000
  int P = N / G;              // 100

  int smem = (int)sizeof(Smem);
  cudaFuncSetAttribute(dgcnn_kernel, cudaFuncAttributeMaxDynamicSharedMemorySize, smem);

  dgcnn_kernel<<<GRID, THREADS, smem>>>(x, W1, b1, W2, b2, W3, b3, W4, b4,
                                        cw1, cb1, cw2, cb2, Wo, bo, out, G, P);
}

// round 15
// speedup vs baseline: 2.8620x; 1.1147x over previous
#include <cuda_runtime.h>
#include <cstdint>

#define THREADS 384
#define NW 12
#define GRID 152

__device__ __forceinline__ unsigned f2tf32u(float f) {
  unsigned u; asm("cvt.rna.tf32.f32 %0, %1;" : "=r"(u) : "f"(f)); return u;
}
__device__ __forceinline__ float tf32f(float f) {
  unsigned u; asm("cvt.rna.tf32.f32 %0, %1;" : "=r"(u) : "f"(f)); return __uint_as_float(u);
}
__device__ __forceinline__ void mma8(float* d, const unsigned* a, unsigned b0, unsigned b1) {
  asm("mma.sync.aligned.m16n8k8.row.col.f32.tf32.tf32.f32 "
      "{%0,%1,%2,%3}, {%4,%5,%6,%7}, {%8,%9}, {%0,%1,%2,%3};"
      : "+f"(d[0]), "+f"(d[1]), "+f"(d[2]), "+f"(d[3])
      : "r"(a[0]), "r"(a[1]), "r"(a[2]), "r"(a[3]), "r"(b0), "r"(b1));
}

// ~110 KB dynamic shared memory, 1 block (12 warps) per SM.
// 1xTF32 + k-row-permuted weights for layers 2..4:
//   A-slot col j of a k-tile maps to feature 8kt+2j (j<4) / 8kt+2(j-4)+1 (j>=4),
//   matching the previous layer's D layout. Re-fragment = register rename.
struct Smem {
  alignas(16) float2 Wf[3][2048];   // [layer][(kt*8+nt)*32+lane] tf32
  alignas(16) float2 W4f[1280];     // layer 4 (NT=5)
  alignas(16) float2 Bf[3][256];    // bias frags [nt*32+lane]
  alignas(16) float2 B4f[160];
  float cw1t[5][16];      // [q][c]
  float cb1[16];
  float cw2t[16][5][32];  // [ci][q][c2]
  float cb2[32];
  float Wo[704];
  float bo2[2];
  alignas(16) float pooled[NW][40];
  alignas(16) float mps[NW][16][16];
  alignas(16) float c2s[NW][352];
};

// One MMA layer: D[2][NT] (16x8 f32 tiles) = A (2x8 tiles) x W^T + b. 1xTF32.
template <int NT>
__device__ __forceinline__ void mma_layer(const float2* __restrict__ Wh,
                                          const float2* __restrict__ Bfr,
                                          float A[2][8][4], float D[2][8][4],
                                          int lane) {
#pragma unroll
  for (int nt = 0; nt < NT; nt++) {
    float2 bb = Bfr[nt * 32 + lane];
#pragma unroll
    for (int mt = 0; mt < 2; mt++) {
      D[mt][nt][0] = bb.x; D[mt][nt][1] = bb.y;
      D[mt][nt][2] = bb.x; D[mt][nt][3] = bb.y;
    }
  }
#pragma unroll
  for (int kt = 0; kt < 8; kt++) {
    unsigned Ah[2][4];
#pragma unroll
    for (int mt = 0; mt < 2; mt++)
#pragma unroll
      for (int i = 0; i < 4; i++)
        Ah[mt][i] = f2tf32u(A[mt][kt][i]);
#pragma unroll
    for (int nt = 0; nt < NT; nt++) {
      float2 bh = Wh[(kt * NT + nt) * 32 + lane];
      unsigned bh0 = __float_as_uint(bh.x), bh1 = __float_as_uint(bh.y);
#pragma unroll
      for (int mt = 0; mt < 2; mt++)
        mma8(D[mt][nt], Ah[mt], bh0, bh1);
    }
  }
}

__global__ void __launch_bounds__(THREADS, 1) dgcnn_kernel(
    const float* __restrict__ x,
    const float* __restrict__ W1, const float* __restrict__ b1,
    const float* __restrict__ W2, const float* __restrict__ b2,
    const float* __restrict__ W3, const float* __restrict__ b3,
    const float* __restrict__ W4, const float* __restrict__ b4,
    const float* __restrict__ cw1, const float* __restrict__ cb1,
    const float* __restrict__ cw2, const float* __restrict__ cb2,
    const float* __restrict__ Wo, const float* __restrict__ bo,
    float* __restrict__ out, int G, int P)
{
  extern __shared__ __align__(16) char smem_raw[];
  Smem& sm = *reinterpret_cast<Smem*>(smem_raw);
  const int tid  = threadIdx.x;
  const int w    = tid >> 5;
  const int lane = tid & 31;
  const int gq   = lane >> 2;   // MMA groupID (row)
  const int tq   = lane & 3;    // MMA threadID (col/k)

  // ---- Stage weight fragments (tf32, pre-swizzled; k-permuted for l>=1) ----
  for (int idx = tid; idx < 3 * 2048; idx += THREADS) {
    int l = idx / 2048, q = idx % 2048;
    int ktnt = q >> 5, ln = q & 31;
    int kt = ktnt >> 3, nt = ktnt & 7;
    int g = ln >> 2, t = ln & 3;
    int n = nt * 8 + g;
    const float* Ws = (l == 0) ? W1 : (l == 1) ? W2 : W3;
    int ka, kb;
    if (l == 0) { ka = kt * 8 + t;     kb = ka + 4; }   // identity (input = x)
    else        { ka = kt * 8 + 2 * t; kb = ka + 1; }   // permuted (input = prev D)
    sm.Wf[l][q] = make_float2(tf32f(Ws[n * 64 + ka]), tf32f(Ws[n * 64 + kb]));
  }
  for (int idx = tid; idx < 1280; idx += THREADS) {
    int ktnt = idx >> 5, ln = idx & 31;
    int kt = ktnt / 5, nt = ktnt % 5;
    int g = ln >> 2, t = ln & 3;
    int n = nt * 8 + g;
    int ka = kt * 8 + 2 * t, kb = ka + 1;               // permuted (input = layer-3 D)
    float w0 = (n < 34) ? W4[n * 64 + ka] : 0.f;
    float w1 = (n < 34) ? W4[n * 64 + kb] : 0.f;
    sm.W4f[idx] = make_float2(tf32f(w0), tf32f(w1));
  }
  for (int idx = tid; idx < 3 * 256; idx += THREADS) {
    int l = idx / 256, q = idx % 256;
    int nt = q >> 5, t = q & 3;
    const float* bs = (l == 0) ? b1 : (l == 1) ? b2 : b3;
    int f = nt * 8 + 2 * t;
    sm.Bf[l][q] = make_float2(bs[f], bs[f + 1]);
  }
  for (int idx = tid; idx < 160; idx += THREADS) {
    int nt = idx >> 5, t = idx & 3;
    int f = nt * 8 + 2 * t;
    sm.B4f[idx] = make_float2((f < 34) ? b4[f] : 0.f, (f + 1 < 34) ? b4[f + 1] : 0.f);
  }
  for (int i = tid; i < 80; i += THREADS) { int q = i >> 4, c = i & 15; sm.cw1t[q][c] = cw1[c * 5 + q]; }
  if (tid < 16)  sm.cb1[tid] = cb1[tid];
  for (int i = tid; i < 2560; i += THREADS) {
    int ci = i / 160, r = i % 160, q = r >> 5, c2 = r & 31;
    sm.cw2t[ci][q][c2] = cw2[(c2 * 16 + ci) * 5 + q];
  }
  if (tid < 32)  sm.cb2[tid] = cb2[tid];
  for (int i = tid; i < 704; i += THREADS) sm.Wo[i] = Wo[i];
  if (tid < 2)   sm.bo2[tid] = bo[tid];
  __syncthreads();

  const int kc = (P < 30) ? P : 30;
  const float inv = 1.f / (float)kc;
  const unsigned FULL = 0xffffffffu;

  for (int g = blockIdx.x * NW + w; g < G; g += GRID * NW) {
    // ---- Load x directly as A-fragments (rows clamped for safety) ----
    float A[2][8][4];
    float D[2][8][4];
    {
      const float* xg = x + (size_t)g * P * 64;
#pragma unroll
      for (int mt = 0; mt < 2; mt++) {
        int r0 = mt * 16 + gq, r1 = r0 + 8;
        if (r0 >= P) r0 = P - 1;
        if (r1 >= P) r1 = P - 1;
        const float* p0 = xg + r0 * 64;
        const float* p1 = xg + r1 * 64;
#pragma unroll
        for (int kt = 0; kt < 8; kt++) {
          int c0 = kt * 8 + tq;
          A[mt][kt][0] = p0[c0];
          A[mt][kt][1] = p1[c0];
          A[mt][kt][2] = p0[c0 + 4];
          A[mt][kt][3] = p1[c0 + 4];
        }
      }
    }

    // ---- Layers 1-3: MMA + relu; re-fragment is a register rename thanks to
    //      the k-row permutation baked into the next layer's weights ----
#pragma unroll 1
    for (int l = 0; l < 3; l++) {
      mma_layer<8>(sm.Wf[l], sm.Bf[l], A, D, lane);
#pragma unroll
      for (int mt = 0; mt < 2; mt++) {
#pragma unroll
        for (int nt = 0; nt < 8; nt++) {
          A[mt][nt][0] = fmaxf(D[mt][nt][0], 0.f);
          A[mt][nt][1] = fmaxf(D[mt][nt][2], 0.f);
          A[mt][nt][2] = fmaxf(D[mt][nt][1], 0.f);
          A[mt][nt][3] = fmaxf(D[mt][nt][3], 0.f);
        }
      }
    }

    // ---- Layer 4 (NT=5, 40 padded cols) + relu + masked mean-pool ----
    {
      mma_layer<5>(sm.W4f, sm.B4f, A, D, lane);
      float m00 = (gq < kc) ? 1.f : 0.f;
      float m01 = (8 + gq < kc) ? 1.f : 0.f;
      float m10 = (16 + gq < kc) ? 1.f : 0.f;
      float m11 = (24 + gq < kc) ? 1.f : 0.f;
      float se[5], so[5];
#pragma unroll
      for (int nt = 0; nt < 5; nt++) {
        se[nt] = m00 * fmaxf(D[0][nt][0], 0.f) + m01 * fmaxf(D[0][nt][2], 0.f)
               + m10 * fmaxf(D[1][nt][0], 0.f) + m11 * fmaxf(D[1][nt][2], 0.f);
        so[nt] = m00 * fmaxf(D[0][nt][1], 0.f) + m01 * fmaxf(D[0][nt][3], 0.f)
               + m10 * fmaxf(D[1][nt][1], 0.f) + m11 * fmaxf(D[1][nt][3], 0.f);
      }
#pragma unroll
      for (int d = 4; d < 32; d <<= 1) {
#pragma unroll
        for (int nt = 0; nt < 5; nt++) {
          se[nt] += __shfl_xor_sync(FULL, se[nt], d);
          so[nt] += __shfl_xor_sync(FULL, so[nt], d);
        }
      }
      if (lane < 4) {   // g == 0 lanes; t = lane
#pragma unroll
        for (int nt = 0; nt < 5; nt++) {
          int f = nt * 8 + 2 * lane;
          if (f < 34)     sm.pooled[w][f]     = se[nt] * inv;
          if (f + 1 < 34) sm.pooled[w][f + 1] = so[nt] * inv;
        }
      }
    }
    __syncwarp();

    // ---- conv1 (16ch,k=5 -> 30) + ReLU + maxpool2 -> mps[16][15] ----
    {
      int c = lane & 15, h = lane >> 4;
      float wq[5];
#pragma unroll
      for (int q = 0; q < 5; q++) wq[q] = sm.cw1t[q][c];
      float bc = sm.cb1[c];
#pragma unroll
      for (int sIdx = 0; sIdx < 15; sIdx++) {
        int t = 2 * sIdx + h;
        float a = bc;
#pragma unroll
        for (int q = 0; q < 5; q++) a = fmaf(wq[q], sm.pooled[w][t + q], a);
        a = fmaxf(a, 0.f);
        float mv = fmaxf(a, __shfl_xor_sync(FULL, a, 16));
        if (h == 0) sm.mps[w][c][sIdx] = mv;
      }
    }
    __syncwarp();

    // ---- conv2 (32ch,16in,k=5 -> 11) + ReLU ----
    {
      int c2 = lane;
      float a11[11];
#pragma unroll
      for (int t = 0; t < 11; t++) a11[t] = sm.cb2[c2];
#pragma unroll
      for (int ci = 0; ci < 16; ci++) {
        const float4* mr = reinterpret_cast<const float4*>(&sm.mps[w][ci][0]);
        float4 Aq = mr[0], Bq = mr[1], Cq = mr[2], Dq = mr[3];
        float m[16] = {Aq.x,Aq.y,Aq.z,Aq.w, Bq.x,Bq.y,Bq.z,Bq.w,
                       Cq.x,Cq.y,Cq.z,Cq.w, Dq.x,Dq.y,Dq.z,Dq.w};
#pragma unroll
        for (int q = 0; q < 5; q++) {
          float wv = sm.cw2t[ci][q][c2];
#pragma unroll
          for (int t = 0; t < 11; t++) a11[t] = fmaf(wv, m[t + q], a11[t]);
        }
      }
#pragma unroll
      for (int t = 0; t < 11; t++) sm.c2s[w][c2 * 11 + t] = fmaxf(a11[t], 0.f);
    }
    __syncwarp();

    // ---- FC 352 -> 2 ----
    {
      float s0 = 0.f, s1 = 0.f;
#pragma unroll
      for (int j = 0; j < 11; j++) {
        int i = lane + 32 * j;
        float c = sm.c2s[w][i];
        s0 = fmaf(sm.Wo[i], c, s0);
        s1 = fmaf(sm.Wo[352 + i], c, s1);
      }
#pragma unroll
      for (int d = 16; d > 0; d >>= 1) {
        s0 += __shfl_xor_sync(FULL, s0, d);
        s1 += __shfl_xor_sync(FULL, s1, d);
      }
      if (lane == 0) {
        out[g * 2 + 0] = s0 + sm.bo2[0];
        out[g * 2 + 1] = s1 + sm.bo2[1];
      }
    }
    __syncwarp();
  }
}

extern "C" void kernel_launch(void* const* d_in, const int* in_sizes, int n_in,
                              void* d_out, int out_size) {
  const float* x   = (const float*)d_in[0];
  // d_in[1] = edge_index (unused by reference), d_in[2] = batch (i // (N/G))
  const float* W1  = (const float*)d_in[3];
  const float* b1  = (const float*)d_in[4];
  const float* W2  = (const float*)d_in[5];
  const float* b2  = (const float*)d_in[6];
  const float* W3  = (const float*)d_in[7];
  const float* b3  = (const float*)d_in[8];
  const float* W4  = (const float*)d_in[9];
  const float* b4  = (const float*)d_in[10];
  const float* cw1 = (const float*)d_in[11];
  const float* cb1 = (const float*)d_in[12];
  const float* cw2 = (const float*)d_in[13];
  const float* cb2 = (const float*)d_in[14];
  const float* Wo  = (const float*)d_in[15];
  const float* bo  = (const float*)d_in[16];
  float* out = (float*)d_out;

  int G = out_size / 2;       // 10000
  int N = in_sizes[0] / 64;   // 1000000
  int P = N / G;              // 100

  int smem = (int)sizeof(Smem);
  cudaFuncSetAttribute(dgcnn_kernel, cudaFuncAttributeMaxDynamicSharedMemorySize, smem);

  dgcnn_kernel<<<GRID, THREADS, smem>>>(x, W1, b1, W2, b2, W3, b3, W4, b4,
                                        cw1, cb1, cw2, cb2, Wo, bo, out, G, P);
}

// round 17
// speedup vs baseline: 4.3621x; 1.5241x over previous
#include <cuda_runtime.h>
#include <cstdint>

#define THREADS 384
#define NW 12
#define GRID 152

// pack two f32 -> f16x2 (first asm src -> high half, so pass (hi, lo))
__device__ __forceinline__ unsigned f16x2(float lo, float hi) {
  unsigned r; asm("cvt.rn.f16x2.f32 %0, %1, %2;" : "=r"(r) : "f"(hi), "f"(lo)); return r;
}
__device__ __forceinline__ void mma16(float* d, const unsigned* a, unsigned b0, unsigned b1) {
  asm("mma.sync.aligned.m16n8k16.row.col.f32.f16.f16.f32 "
      "{%0,%1,%2,%3}, {%4,%5,%6,%7}, {%8,%9}, {%0,%1,%2,%3};"
      : "+f"(d[0]), "+f"(d[1]), "+f"(d[2]), "+f"(d[3])
      : "r"(a[0]), "r"(a[1]), "r"(a[2]), "r"(a[3]), "r"(b0), "r"(b1));
}

// ~80 KB dynamic shared memory, 1 block (12 warps) per SM.
// 1xFP16 m16n8k16: fp16 mantissa (11 bits) == tf32, so error matches the
// measured 1xTF32 point (1.79e-4) while running at half-precision MMA rate.
// Activation magnitudes (~0.1 .. 4e-4 across layers) sit inside fp16 normal range.
struct Smem {
  alignas(16) uint2 Wb[3][1024];   // [layer][(kt*8+nt)*32+lane], kt<4
  alignas(16) uint2 W4b[640];      // layer 4 (NT=5): (kt*5+nt)*32+lane
  alignas(16) float2 Bf[3][256];   // bias frags [nt*32+lane] = (b[8nt+2tq], b[8nt+2tq+1])
  alignas(16) float2 B4f[160];
  float cw1t[5][16];      // [q][c]
  float cb1[16];
  float cw2t[16][5][32];  // [ci][q][c2]
  float cb2[32];
  float Wo[704];
  float bo2[2];
  alignas(16) float pooled[NW][40];
  alignas(16) float mps[NW][16][16];
  alignas(16) float c2s[NW][352];
};

// One fp16 MMA layer: D[2][NT] = A (2 x 4 k16-tiles) x W^T + b.
template <int NT>
__device__ __forceinline__ void mma_layer(const uint2* __restrict__ Wb,
                                          const float2* __restrict__ Bfr,
                                          unsigned Aq[2][4][4], float D[2][8][4],
                                          int lane) {
#pragma unroll
  for (int nt = 0; nt < NT; nt++) {
    float2 bb = Bfr[nt * 32 + lane];
#pragma unroll
    for (int mt = 0; mt < 2; mt++) {
      D[mt][nt][0] = bb.x; D[mt][nt][1] = bb.y;
      D[mt][nt][2] = bb.x; D[mt][nt][3] = bb.y;
    }
  }
#pragma unroll
  for (int kt = 0; kt < 4; kt++) {
#pragma unroll
    for (int nt = 0; nt < NT; nt++) {
      uint2 b = Wb[(kt * NT + nt) * 32 + lane];
#pragma unroll
      for (int mt = 0; mt < 2; mt++)
        mma16(D[mt][nt], Aq[mt][kt], b.x, b.y);
    }
  }
}

__global__ void __launch_bounds__(THREADS, 1) dgcnn_kernel(
    const float* __restrict__ x,
    const float* __restrict__ W1, const float* __restrict__ b1,
    const float* __restrict__ W2, const float* __restrict__ b2,
    const float* __restrict__ W3, const float* __restrict__ b3,
    const float* __restrict__ W4, const float* __restrict__ b4,
    const float* __restrict__ cw1, const float* __restrict__ cb1,
    const float* __restrict__ cw2, const float* __restrict__ cb2,
    const float* __restrict__ Wo, const float* __restrict__ bo,
    float* __restrict__ out, int G, int P)
{
  extern __shared__ __align__(16) char smem_raw[];
  Smem& sm = *reinterpret_cast<Smem*>(smem_raw);
  const int tid  = threadIdx.x;
  const int w    = tid >> 5;
  const int lane = tid & 31;
  const int gq   = lane >> 2;   // MMA groupID (row / n)
  const int tq   = lane & 3;    // MMA threadID (k pairs)

  // ---- Stage fp16 weight fragments ----
  // frag (kt,nt,lane): n = nt*8+gq, k0 = kt*16+2tq;
  // b.x = {W[n][k0] lo, W[n][k0+1] hi}; b.y = same at k0+8.
  for (int idx = tid; idx < 3 * 1024; idx += THREADS) {
    int l = idx >> 10, q = idx & 1023;
    int ktnt = q >> 5, ln = q & 31;
    int kt = ktnt >> 3, nt = ktnt & 7;
    int g = ln >> 2, t = ln & 3;
    int n = nt * 8 + g, k0 = kt * 16 + 2 * t;
    const float* Ws = (l == 0) ? W1 : (l == 1) ? W2 : W3;
    sm.Wb[l][q] = make_uint2(f16x2(Ws[n * 64 + k0],     Ws[n * 64 + k0 + 1]),
                             f16x2(Ws[n * 64 + k0 + 8], Ws[n * 64 + k0 + 9]));
  }
  for (int idx = tid; idx < 640; idx += THREADS) {
    int ktnt = idx >> 5, ln = idx & 31;
    int kt = ktnt / 5, nt = ktnt % 5;
    int g = ln >> 2, t = ln & 3;
    int n = nt * 8 + g, k0 = kt * 16 + 2 * t;
    float w0 = 0.f, w1 = 0.f, w2 = 0.f, w3 = 0.f;
    if (n < 34) {
      w0 = W4[n * 64 + k0];     w1 = W4[n * 64 + k0 + 1];
      w2 = W4[n * 64 + k0 + 8]; w3 = W4[n * 64 + k0 + 9];
    }
    sm.W4b[idx] = make_uint2(f16x2(w0, w1), f16x2(w2, w3));
  }
  for (int idx = tid; idx < 3 * 256; idx += THREADS) {
    int l = idx / 256, q = idx % 256;
    int nt = q >> 5, t = q & 3;
    const float* bs = (l == 0) ? b1 : (l == 1) ? b2 : b3;
    int f = nt * 8 + 2 * t;
    sm.Bf[l][q] = make_float2(bs[f], bs[f + 1]);
  }
  for (int idx = tid; idx < 160; idx += THREADS) {
    int nt = idx >> 5, t = idx & 3;
    int f = nt * 8 + 2 * t;
    sm.B4f[idx] = make_float2((f < 34) ? b4[f] : 0.f, (f + 1 < 34) ? b4[f + 1] : 0.f);
  }
  for (int i = tid; i < 80; i += THREADS) { int q = i >> 4, c = i & 15; sm.cw1t[q][c] = cw1[c * 5 + q]; }
  if (tid < 16)  sm.cb1[tid] = cb1[tid];
  for (int i = tid; i < 2560; i += THREADS) {
    int ci = i / 160, r = i % 160, q = r >> 5, c2 = r & 31;
    sm.cw2t[ci][q][c2] = cw2[(c2 * 16 + ci) * 5 + q];
  }
  if (tid < 32)  sm.cb2[tid] = cb2[tid];
  for (int i = tid; i < 704; i += THREADS) sm.Wo[i] = Wo[i];
  if (tid < 2)   sm.bo2[tid] = bo[tid];
  __syncthreads();

  const int kc = (P < 30) ? P : 30;
  const float inv = 1.f / (float)kc;
  const unsigned FULL = 0xffffffffu;

  for (int g = blockIdx.x * NW + w; g < G; g += GRID * NW) {
    // ---- Load x as packed fp16 A-fragments (float2 gmem loads) ----
    unsigned Aq[2][4][4];
    float D[2][8][4];
    {
      const float* xg = x + (size_t)g * P * 64;
#pragma unroll
      for (int mt = 0; mt < 2; mt++) {
        int r0 = mt * 16 + gq, r1 = r0 + 8;
        if (r0 >= P) r0 = P - 1;
        if (r1 >= P) r1 = P - 1;
        const float* p0 = xg + r0 * 64;
        const float* p1 = xg + r1 * 64;
#pragma unroll
        for (int kt = 0; kt < 4; kt++) {
          int k0 = kt * 16 + 2 * tq;
          float2 v00 = *reinterpret_cast<const float2*>(p0 + k0);
          float2 v10 = *reinterpret_cast<const float2*>(p1 + k0);
          float2 v01 = *reinterpret_cast<const float2*>(p0 + k0 + 8);
          float2 v11 = *reinterpret_cast<const float2*>(p1 + k0 + 8);
          Aq[mt][kt][0] = f16x2(v00.x, v00.y);
          Aq[mt][kt][1] = f16x2(v10.x, v10.y);
          Aq[mt][kt][2] = f16x2(v01.x, v01.y);
          Aq[mt][kt][3] = f16x2(v11.x, v11.y);
        }
      }
    }

    // ---- Layers 1-3: MMA + relu + direct register re-pack ----
    // A k16-tile kt covers feats 16kt..16kt+15 = D tiles 2kt (cols 0..7) and 2kt+1.
#pragma unroll 1
    for (int l = 0; l < 3; l++) {
      mma_layer<8>(sm.Wb[l], sm.Bf[l], Aq, D, lane);
#pragma unroll
      for (int mt = 0; mt < 2; mt++) {
#pragma unroll
        for (int kt = 0; kt < 4; kt++) {
          Aq[mt][kt][0] = f16x2(fmaxf(D[mt][2*kt][0], 0.f),   fmaxf(D[mt][2*kt][1], 0.f));
          Aq[mt][kt][1] = f16x2(fmaxf(D[mt][2*kt][2], 0.f),   fmaxf(D[mt][2*kt][3], 0.f));
          Aq[mt][kt][2] = f16x2(fmaxf(D[mt][2*kt+1][0], 0.f), fmaxf(D[mt][2*kt+1][1], 0.f));
          Aq[mt][kt][3] = f16x2(fmaxf(D[mt][2*kt+1][2], 0.f), fmaxf(D[mt][2*kt+1][3], 0.f));
        }
      }
    }

    // ---- Layer 4 (NT=5, 40 padded cols) + relu + masked mean-pool ----
    {
      mma_layer<5>(sm.W4b, sm.B4f, Aq, D, lane);
      float m00 = (gq < kc) ? 1.f : 0.f;
      float m01 = (8 + gq < kc) ? 1.f : 0.f;
      float m10 = (16 + gq < kc) ? 1.f : 0.f;
      float m11 = (24 + gq < kc) ? 1.f : 0.f;
      float se[5], so[5];
#pragma unroll
      for (int nt = 0; nt < 5; nt++) {
        se[nt] = m00 * fmaxf(D[0][nt][0], 0.f) + m01 * fmaxf(D[0][nt][2], 0.f)
               + m10 * fmaxf(D[1][nt][0], 0.f) + m11 * fmaxf(D[1][nt][2], 0.f);
        so[nt] = m00 * fmaxf(D[0][nt][1], 0.f) + m01 * fmaxf(D[0][nt][3], 0.f)
               + m10 * fmaxf(D[1][nt][1], 0.f) + m11 * fmaxf(D[1][nt][3], 0.f);
      }
#pragma unroll
      for (int d = 4; d < 32; d <<= 1) {
#pragma unroll
        for (int nt = 0; nt < 5; nt++) {
          se[nt] += __shfl_xor_sync(FULL, se[nt], d);
          so[nt] += __shfl_xor_sync(FULL, so[nt], d);
        }
      }
      if (lane < 4) {   // gq == 0 lanes; tq = lane
#pragma unroll
        for (int nt = 0; nt < 5; nt++) {
          int f = nt * 8 + 2 * lane;
          if (f < 34)     sm.pooled[w][f]     = se[nt] * inv;
          if (f + 1 < 34) sm.pooled[w][f + 1] = so[nt] * inv;
        }
      }
    }
    __syncwarp();

    // ---- conv1 (16ch,k=5 -> 30) + ReLU + maxpool2 -> mps[16][15] ----
    {
      int c = lane & 15, h = lane >> 4;
      float wq[5];
#pragma unroll
      for (int q = 0; q < 5; q++) wq[q] = sm.cw1t[q][c];
      float bc = sm.cb1[c];
#pragma unroll
      for (int sIdx = 0; sIdx < 15; sIdx++) {
        int t = 2 * sIdx + h;
        float a = bc;
#pragma unroll
        for (int q = 0; q < 5; q++) a = fmaf(wq[q], sm.pooled[w][t + q], a);
        a = fmaxf(a, 0.f);
        float mv = fmaxf(a, __shfl_xor_sync(FULL, a, 16));
        if (h == 0) sm.mps[w][c][sIdx] = mv;
      }
    }
    __syncwarp();

    // ---- conv2 (32ch,16in,k=5 -> 11) + ReLU ----
    {
      int c2 = lane;
      float a11[11];
#pragma unroll
      for (int t = 0; t < 11; t++) a11[t] = sm.cb2[c2];
#pragma unroll
      for (int ci = 0; ci < 16; ci++) {
        const float4* mr = reinterpret_cast<const float4*>(&sm.mps[w][ci][0]);
        float4 Aq4 = mr[0], Bq = mr[1], Cq = mr[2], Dq = mr[3];
        float m[16] = {Aq4.x,Aq4.y,Aq4.z,Aq4.w, Bq.x,Bq.y,Bq.z,Bq.w,
                       Cq.x,Cq.y,Cq.z,Cq.w, Dq.x,Dq.y,Dq.z,Dq.w};
#pragma unroll
        for (int q = 0; q < 5; q++) {
          float wv = sm.cw2t[ci][q][c2];
#pragma unroll
          for (int t = 0; t < 11; t++) a11[t] = fmaf(wv, m[t + q], a11[t]);
        }
      }
#pragma unroll
      for (int t = 0; t < 11; t++) sm.c2s[w][c2 * 11 + t] = fmaxf(a11[t], 0.f);
    }
    __syncwarp();

    // ---- FC 352 -> 2 ----
    {
      float s0 = 0.f, s1 = 0.f;
#pragma unroll
      for (int j = 0; j < 11; j++) {
        int i = lane + 32 * j;
        float c = sm.c2s[w][i];
        s0 = fmaf(sm.Wo[i], c, s0);
        s1 = fmaf(sm.Wo[352 + i], c, s1);
      }
#pragma unroll
      for (int d = 16; d > 0; d >>= 1) {
        s0 += __shfl_xor_sync(FULL, s0, d);
        s1 += __shfl_xor_sync(FULL, s1, d);
      }
      if (lane == 0) {
        out[g * 2 + 0] = s0 + sm.bo2[0];
        out[g * 2 + 1] = s1 + sm.bo2[1];
      }
    }
    __syncwarp();
  }
}

extern "C" void kernel_launch(void* const* d_in, const int* in_sizes, int n_in,
                              void* d_out, int out_size) {
  const float* x   = (const float*)d_in[0];
  // d_in[1] = edge_index (unused by reference), d_in[2] = batch (i // (N/G))
  const float* W1  = (const float*)d_in[3];
  const float* b1  = (const float*)d_in[4];
  const float* W2  = (const float*)d_in[5];
  const float* b2  = (const float*)d_in[6];
  const float* W3  = (const float*)d_in[7];
  const float* b3  = (const float*)d_in[8];
  const float* W4  = (const float*)d_in[9];
  const float* b4  = (const float*)d_in[10];
  const float* cw1 = (const float*)d_in[11];
  const float* cb1 = (const float*)d_in[12];
  const float* cw2 = (const float*)d_in[13];
  const float* cb2 = (const float*)d_in[14];
  const float* Wo  = (const float*)d_in[15];
  const float* bo  = (const float*)d_in[16];
  float* out = (float*)d_out;

  int G = out_size / 2;       // 10000
  int N = in_sizes[0] / 64;   // 1000000
  int P = N / G;              // 100

  int smem = (int)sizeof(Smem);
  cudaFuncSetAttribute(dgcnn_kernel, cudaFuncAttributeMaxDynamicSharedMemorySize, smem);

  dgcnn_kernel<<<GRID, THREADS, smem>>>(x, W1, b1, W2, b2, W3, b3, W4, b4,
                                        cw1, cb1, cw2, cb2, Wo, bo, out, G, P);
}